// round 11
// baseline (speedup 1.0000x reference)
#include <cuda_runtime.h>
#include <cuda_fp16.h>
#include <math.h>
#include <stdint.h>

// ---------------- problem constants ----------------
#define BB 4
#define LL 2048
#define DD 512
#define DRR 256
#define RR 3
#define PP 5
#define PHH 3
#define FF 1536
#define NTOK (BB*LL)            // 8192
#define RDR (RR*DRR)            // 768

// ---------------- device scratch ----------------
__device__ __align__(256) float g_res[NTOK*DD];
__device__ __align__(256) float g_delta[NTOK*DD];
__device__ __align__(256) float g_sc[NTOK];
__device__ __align__(256) float g_part[128*DD];
__device__ __align__(256) float g_part1[64*FF];
__device__ __align__(256) float g_hsum[FF];
__device__ __align__(256) float g_q[DD];
__device__ __align__(256) float g_kq[DD];
__device__ __align__(256) float g_wxm[DD];
__device__ __align__(256) float g_summ[DD];
__device__ __align__(256) float g_regsA[RDR];
__device__ __align__(256) float g_regsB[RDR];
__device__ __align__(256) float g_gate[DD];
__device__ __align__(256) float g_banks[PP*RDR];
__device__ __align__(256) float g_pw[16];
__device__ __align__(256) float g_wxb[BB*DD];
__device__ __align__(256) float g_ms1[BB*DD];
__device__ __align__(256) float g_mo[BB*DD];
__device__ __align__(256) int   g_cnt[64];

__device__ __align__(256) __half g_xnatt[NTOK*DD];
__device__ __align__(256) __half g_xnh[NTOK*DD];
__device__ __align__(256) __half g_hh[NTOK*FF];
__device__ __align__(256) __half g_w1th[PHH*FF*DD];
__device__ __align__(256) __half g_w2th[PHH*DD*FF];

// ---------------- PTX helpers ----------------
__device__ __forceinline__ uint32_t smem_u32(const void* p) {
    return (uint32_t)__cvta_generic_to_shared(p);
}
__device__ __forceinline__ void cpasync16(uint32_t dst, const void* src) {
    asm volatile("cp.async.cg.shared.global [%0], [%1], 16;" :: "r"(dst), "l"(src) : "memory");
}
__device__ __forceinline__ void cp_commit() {
    asm volatile("cp.async.commit_group;" ::: "memory");
}
__device__ __forceinline__ void cp_wait1() {
    asm volatile("cp.async.wait_group 1;" ::: "memory");
}
__device__ __forceinline__ void ldsm4(uint32_t* r, uint32_t addr) {
    asm volatile("ldmatrix.sync.aligned.m8n8.x4.shared.b16 {%0,%1,%2,%3}, [%4];"
                 : "=r"(r[0]), "=r"(r[1]), "=r"(r[2]), "=r"(r[3]) : "r"(addr));
}
__device__ __forceinline__ void mma16816(float* c, const uint32_t* a, uint32_t b0, uint32_t b1) {
    asm volatile(
        "mma.sync.aligned.m16n8k16.row.col.f32.f16.f16.f32 "
        "{%0,%1,%2,%3}, {%4,%5,%6,%7}, {%8,%9}, {%0,%1,%2,%3};"
        : "+f"(c[0]), "+f"(c[1]), "+f"(c[2]), "+f"(c[3])
        : "r"(a[0]), "r"(a[1]), "r"(a[2]), "r"(a[3]), "r"(b0), "r"(b1));
}

// ---------------- fp16 GEMM via mma.sync ----------------
// MODE 1 (GEMM1): Ch = fp16(gelu(acc+bias)); part1 colsum; then threadfence +
//                 atomicAdd(cnt[by]) — signals row-block ready for GEMM2.
// MODE 0 (GEMM2): spins at entry until cnt[by] >= target (row ready), then
//                 Cf = acc + bias (delta). Launched on a low-priority stream,
//                 fills GEMM1's tail-wave slots.
#define STAGE_BYTES 32768
#define NSTAGE 3

template <int OUTMODE>
__global__ void __launch_bounds__(256, 2)
mmagemm_kernel(const __half* __restrict__ Ah, const __half* __restrict__ Bh,
               const float* __restrict__ bias,
               __half* __restrict__ Ch, float* __restrict__ part1,
               float* __restrict__ Cf,
               int* cnt, int target,
               int M, int N, int K) {
    extern __shared__ __align__(128) unsigned char smem[];

    const int tid  = threadIdx.x;
    const int wid  = tid >> 5;
    const int lane = tid & 31;
    const int n0 = blockIdx.x * 128;
    const int m0 = blockIdx.y * 128;
    const int NIT = K >> 6;
    const uint32_t smem_base = smem_u32(smem);

    if (OUTMODE == 0) {
        // wait until all 12 GEMM1 column tiles of this row block are done
        if (tid == 0) {
            volatile int* c = (volatile int*)(cnt + blockIdx.y);
            while (*c < target) __nanosleep(64);
        }
        __syncthreads();
    }

    int lrowA[4]; int lcA[4]; uint32_t ldst[4];
    #pragma unroll
    for (int u = 0; u < 4; u++) {
        int s = tid + u * 256;
        int row = s >> 3, c = s & 7;
        lrowA[u] = row; lcA[u] = c;
        ldst[u] = (uint32_t)(row * 128 + ((c ^ (row & 7)) << 4));
    }

    auto prefetch = [&](int it) {
        const int k0 = it << 6;
        const uint32_t st = smem_base + (uint32_t)(it % NSTAGE) * STAGE_BYTES;
        #pragma unroll
        for (int u = 0; u < 4; u++)
            cpasync16(st + ldst[u], Ah + (size_t)(m0 + lrowA[u]) * K + k0 + lcA[u] * 8);
        #pragma unroll
        for (int u = 0; u < 4; u++)
            cpasync16(st + 16384 + ldst[u], Bh + (size_t)(n0 + lrowA[u]) * K + k0 + lcA[u] * 8);
        cp_commit();
    };

    float acc[2][8][4];
    #pragma unroll
    for (int i = 0; i < 2; i++)
        #pragma unroll
        for (int j = 0; j < 8; j++)
            #pragma unroll
            for (int t = 0; t < 4; t++) acc[i][j][t] = 0.f;

    const int wm = (wid & 3) * 32;
    const int wn = (wid >> 2) * 64;
    const int lrow = lane & 15;
    const int lseg = lane >> 4;

    prefetch(0);
    if (NIT > 1) prefetch(1);

    #pragma unroll 1
    for (int it = 0; it < NIT; it++) {
        cp_wait1();
        __syncthreads();
        if (it + 2 < NIT) prefetch(it + 2);

        const uint32_t st = smem_base + (uint32_t)(it % NSTAGE) * STAGE_BYTES;
        #pragma unroll
        for (int kk = 0; kk < 4; kk++) {
            uint32_t af[2][4];
            #pragma unroll
            for (int i = 0; i < 2; i++) {
                int row = wm + i * 16 + lrow;
                int seg = kk * 2 + lseg;
                ldsm4(af[i], st + (uint32_t)(row * 128 + (((seg ^ (row & 7))) << 4)));
            }
            uint32_t bf[4][4];
            #pragma unroll
            for (int g = 0; g < 4; g++) {
                int row = wn + g * 16 + lrow;
                int seg = kk * 2 + lseg;
                ldsm4(bf[g], st + 16384u + (uint32_t)(row * 128 + (((seg ^ (row & 7))) << 4)));
            }
            #pragma unroll
            for (int i = 0; i < 2; i++)
                #pragma unroll
                for (int j = 0; j < 8; j++) {
                    int g = j >> 1, w = j & 1;
                    mma16816(acc[i][j], af[i], bf[g][w], bf[g][w + 2]);
                }
        }
    }

    const int l4 = lane >> 2;
    const int l2 = (lane & 3) * 2;

    if (OUTMODE == 1) {
        float vg[2][8][4];
        #pragma unroll
        for (int i = 0; i < 2; i++)
            #pragma unroll
            for (int j = 0; j < 8; j++) {
                const int col = n0 + wn + j * 8 + l2;
                const float b0v = bias[col], b1v = bias[col + 1];
                float t0 = acc[i][j][0] + b0v, t1 = acc[i][j][1] + b1v;
                float t2 = acc[i][j][2] + b0v, t3 = acc[i][j][3] + b1v;
                vg[i][j][0] = 0.5f * t0 * (1.0f + erff(t0 * 0.70710678118654752f));
                vg[i][j][1] = 0.5f * t1 * (1.0f + erff(t1 * 0.70710678118654752f));
                vg[i][j][2] = 0.5f * t2 * (1.0f + erff(t2 * 0.70710678118654752f));
                vg[i][j][3] = 0.5f * t3 * (1.0f + erff(t3 * 0.70710678118654752f));
            }
        float cs0[8], cs1[8];
        #pragma unroll
        for (int j = 0; j < 8; j++) {
            cs0[j] = vg[0][j][0] + vg[0][j][2] + vg[1][j][0] + vg[1][j][2];
            cs1[j] = vg[0][j][1] + vg[0][j][3] + vg[1][j][1] + vg[1][j][3];
            #pragma unroll
            for (int off = 4; off <= 16; off <<= 1) {
                cs0[j] += __shfl_xor_sync(0xffffffffu, cs0[j], off);
                cs1[j] += __shfl_xor_sync(0xffffffffu, cs1[j], off);
            }
        }
        __syncthreads();
        float* cs = (float*)smem;
        if (lane < 4) {
            #pragma unroll
            for (int j = 0; j < 8; j++) {
                cs[wid * 64 + j * 8 + lane * 2 + 0] = cs0[j];
                cs[wid * 64 + j * 8 + lane * 2 + 1] = cs1[j];
            }
        }
        __syncthreads();
        if (tid < 128) {
            int ng = tid >> 6, cw = tid & 63;
            float s = cs[(ng * 4 + 0) * 64 + cw] + cs[(ng * 4 + 1) * 64 + cw]
                    + cs[(ng * 4 + 2) * 64 + cw] + cs[(ng * 4 + 3) * 64 + cw];
            part1[(size_t)blockIdx.y * FF + n0 + ng * 64 + cw] = s;
        }
        #pragma unroll
        for (int i = 0; i < 2; i++)
            #pragma unroll
            for (int j = 0; j < 8; j++) {
                const int col = n0 + wn + j * 8 + l2;
                const int row0 = m0 + wm + i * 16 + l4;
                unsigned short h0 = __half_as_ushort(__float2half_rn(vg[i][j][0]));
                unsigned short h1 = __half_as_ushort(__float2half_rn(vg[i][j][1]));
                unsigned short h2 = __half_as_ushort(__float2half_rn(vg[i][j][2]));
                unsigned short h3 = __half_as_ushort(__float2half_rn(vg[i][j][3]));
                *(ushort2*)((unsigned short*)Ch + (size_t)row0 * N + col)       = make_ushort2(h0, h1);
                *(ushort2*)((unsigned short*)Ch + (size_t)(row0 + 8) * N + col) = make_ushort2(h2, h3);
            }
        // signal this row block complete
        __threadfence();
        __syncthreads();
        if (tid == 0) atomicAdd(cnt + blockIdx.y, 1);
    } else {
        #pragma unroll
        for (int i = 0; i < 2; i++)
            #pragma unroll
            for (int j = 0; j < 8; j++) {
                const int col = n0 + wn + j * 8 + l2;
                const int row0 = m0 + wm + i * 16 + l4;
                const float b0v = bias[col], b1v = bias[col + 1];
                *(float2*)(Cf + (size_t)row0 * N + col) =
                    make_float2(acc[i][j][0] + b0v, acc[i][j][1] + b1v);
                *(float2*)(Cf + (size_t)(row0 + 8) * N + col) =
                    make_float2(acc[i][j][2] + b0v, acc[i][j][3] + b1v);
            }
    }
}

// ---------------- fused residual-update + LayerNorm ----------------
template <int INMODE, int XNMODE, int EMIT_XNH>
__global__ void lnx_kernel(float* __restrict__ res,
                           const float* __restrict__ delta, const float* __restrict__ gate,
                           const float* __restrict__ pw, int p,
                           const float* __restrict__ mo,
                           const float* __restrict__ sA, const float* __restrict__ bA,
                           const float* __restrict__ kq, float* __restrict__ score,
                           __half* __restrict__ xn, float* __restrict__ outf,
                           const float* __restrict__ sB, const float* __restrict__ bB,
                           __half* __restrict__ xnh) {
    __shared__ float red[256];
    int t = blockIdx.x;
    int tid = threadIdx.x;
    float2 v = ((const float2*)res)[(size_t)t * 256 + tid];
    if (INMODE == 1) {
        float w = pw[p];
        float2 d = ((const float2*)delta)[(size_t)t * 256 + tid];
        float2 g = ((const float2*)gate)[tid];
        v.x += w * g.x * d.x;
        v.y += w * g.y * d.y;
        ((float2*)res)[(size_t)t * 256 + tid] = v;
    } else if (INMODE == 2) {
        int b = t >> 11;
        float2 m = ((const float2*)mo)[(b << 8) + tid];
        v.x += m.x; v.y += m.y;
    }
    red[tid] = v.x + v.y; __syncthreads();
    #pragma unroll
    for (int o = 128; o > 0; o >>= 1) { if (tid < o) red[tid] += red[tid + o]; __syncthreads(); }
    float mean = red[0] * (1.0f / 512.0f);
    __syncthreads();
    float d0 = v.x - mean, d1 = v.y - mean;
    red[tid] = d0 * d0 + d1 * d1; __syncthreads();
    #pragma unroll
    for (int o = 128; o > 0; o >>= 1) { if (tid < o) red[tid] += red[tid + o]; __syncthreads(); }
    float rstd = rsqrtf(red[0] * (1.0f / 512.0f) + 1e-5f);
    __syncthreads();
    if (XNMODE) {
        float2 s = ((const float2*)sA)[tid];
        float2 b = ((const float2*)bA)[tid];
        float y0 = d0 * rstd * s.x + b.x;
        float y1 = d1 * rstd * s.y + b.y;
        if (XNMODE == 1) {
            ((__half2*)xn)[(size_t)t * 256 + tid] =
                __halves2half2(__float2half_rn(y0), __float2half_rn(y1));
            float2 k = ((const float2*)kq)[tid];
            red[tid] = y0 * k.x + y1 * k.y; __syncthreads();
            #pragma unroll
            for (int o = 128; o > 0; o >>= 1) { if (tid < o) red[tid] += red[tid + o]; __syncthreads(); }
            if (tid == 0) score[t] = red[0] * 0.044194173824159216f;
        } else {
            ((float2*)outf)[(size_t)t * 256 + tid] = make_float2(y0, y1);
        }
    }
    if (EMIT_XNH) {
        float2 s = ((const float2*)sB)[tid];
        float2 b = ((const float2*)bB)[tid];
        float z0 = d0 * rstd * s.x + b.x;
        float z1 = d1 * rstd * s.y + b.y;
        ((__half2*)xnh)[(size_t)t * 256 + tid] =
            __halves2half2(__float2half_rn(z0), __float2half_rn(z1));
    }
}

// ---------------- hsum: column sums of part1 (64 x 1536) ----------------
__global__ void colsumH_kernel(const float* __restrict__ part1, float* __restrict__ hsum) {
    int col = blockIdx.x * 512 + threadIdx.x;
    float acc = 0.f;
    #pragma unroll 8
    for (int c = 0; c < 64; c++)
        acc += part1[(size_t)c * FF + col];
    hsum[col] = acc;
}

// ---------------- summary: summ[j] = hsum@w2[:,j]/NTOK + b2[j] ----------------
__global__ void summk_kernel(const float* __restrict__ hsum, const __half* __restrict__ w2t,
                             const float* __restrict__ b2, float* __restrict__ summ) {
    __shared__ float red[128];
    int j = blockIdx.x;
    int tid = threadIdx.x;
    const __half* row = w2t + (size_t)j * FF;
    float acc = 0.f;
    #pragma unroll
    for (int k = tid; k < FF; k += 128)
        acc += hsum[k] * __half2float(row[k]);
    red[tid] = acc; __syncthreads();
    #pragma unroll
    for (int o = 64; o > 0; o >>= 1) { if (tid < o) red[tid] += red[tid + o]; __syncthreads(); }
    if (tid == 0) summ[j] = red[0] * (1.0f / (float)NTOK) + b2[j];
}

// ---------------- gate + register update (11 blocks x 512) ----------------
__global__ void gatereg_kernel(const float* __restrict__ summ, const float* __restrict__ regs_cur,
                               const float* __restrict__ gM, const float* __restrict__ gb,
                               float* __restrict__ gate,
                               const float* __restrict__ Wp, const float* __restrict__ Wg,
                               const float* __restrict__ bg,
                               float* __restrict__ regs_next, float* __restrict__ banks) {
    __shared__ float red[512];
    int tid = threadIdx.x;
    if (blockIdx.x < 8) {
        int j = blockIdx.x * 64 + (tid & 63);
        int s = tid >> 6;
        float a = 0.f;
        #pragma unroll 8
        for (int d = s * 160; d < s * 160 + 160; d++) {
            float v = (d < RDR) ? regs_cur[d] : summ[d - RDR];
            a += v * gM[(size_t)d * DD + j];
        }
        red[tid] = a; __syncthreads();
        if (tid < 64) {
            float g = 0.f;
            #pragma unroll
            for (int k = 0; k < 8; k++) g += red[k * 64 + tid];
            g += gb[j];
            gate[j] = 1.f / (1.f + expf(-g));
        }
    } else {
        __shared__ float shw;
        int r = blockIdx.x - 8;
        red[tid] = summ[tid] * Wg[(size_t)r * DD + tid];
        __syncthreads();
        #pragma unroll
        for (int o = 256; o > 0; o >>= 1) { if (tid < o) red[tid] += red[tid + o]; __syncthreads(); }
        if (tid == 0) shw = 1.f / (1.f + expf(-(red[0] + bg[r])));
        __syncthreads();
        int k = tid & 255, s = tid >> 8;
        const float* W = Wp + (size_t)r * DD * DRR;
        float a = 0.f;
        #pragma unroll 16
        for (int d = s * 256; d < (s + 1) * 256; d++)
            a += summ[d] * W[(size_t)d * DRR + k];
        red[tid] = a; __syncthreads();
        if (tid < 256) {
            float nv = regs_cur[r * DRR + k] + shw * (red[k] + red[k + 256]);
            regs_next[r * DRR + k] = nv;
            if (banks) banks[r * DRR + k] = nv;
        }
    }
}

// ---------------- k-split vec @ mat (fp32) ----------------
__global__ void vecmat_split_kernel(const float* __restrict__ v, const float* __restrict__ M,
                                    const float* __restrict__ bias, const float* __restrict__ init,
                                    float* __restrict__ out, int nrow, int ncol, int act) {
    __shared__ float red[512];
    int tid = threadIdx.x;
    int j = blockIdx.x * 64 + (tid & 63);
    int s = tid >> 6;
    int sl = nrow >> 3;
    float acc = 0.f;
    #pragma unroll 16
    for (int d = s * sl; d < (s + 1) * sl; d++)
        acc += v[d] * M[(size_t)d * ncol + j];
    red[tid] = acc; __syncthreads();
    if (tid < 64) {
        float a = 0.f;
        #pragma unroll
        for (int k = 0; k < 8; k++) a += red[k * 64 + tid];
        if (bias) a += bias[j];
        if (init) a += init[j];
        if (act == 1) a = 1.f / (1.f + expf(-a));
        out[j] = a;
    }
}

// batched (4x) 512x512 vec@mat: out[b*512+j] = v[b*512+:] @ M
__global__ void vecmat_b4_kernel(const float* __restrict__ v, const float* __restrict__ M,
                                 float* __restrict__ out) {
    __shared__ float red[512];
    int tid = threadIdx.x;
    int b = blockIdx.y;
    int j = blockIdx.x * 64 + (tid & 63);
    int s = tid >> 6;
    const float* vb = v + (size_t)b * DD;
    float acc = 0.f;
    #pragma unroll 16
    for (int d = s * 64; d < (s + 1) * 64; d++)
        acc += vb[d] * M[(size_t)d * DD + j];
    red[tid] = acc; __syncthreads();
    if (tid < 64) {
        float a = 0.f;
        #pragma unroll
        for (int k = 0; k < 8; k++) a += red[k * 64 + tid];
        out[(size_t)b * DD + j] = a;
    }
}

// ---------------- other small kernels ----------------

__global__ void transpose_all_kernel(const float* __restrict__ w1, const float* __restrict__ w2,
                                     __half* __restrict__ w1t, __half* __restrict__ w2t) {
    __shared__ float tl[32][33];
    int bid = blockIdx.x;
    int m = bid / 768;
    int t = bid % 768;
    const float* src; __half* dst; int R, C;
    if (m < 3) { src = w1 + (size_t)m * DD * FF; dst = w1t + (size_t)m * FF * DD; R = DD; C = FF; }
    else { int ph = m - 3; src = w2 + (size_t)ph * FF * DD; dst = w2t + (size_t)ph * DD * FF; R = FF; C = DD; }
    int tpr = C >> 5;
    int ty = t / tpr, tx = t % tpr;
    int r = ty * 32 + threadIdx.y, c = tx * 32 + threadIdx.x;
    tl[threadIdx.y][threadIdx.x] = src[(size_t)r * C + c];
    __syncthreads();
    int orow = tx * 32 + threadIdx.y, ocol = ty * 32 + threadIdx.x;
    dst[(size_t)orow * R + ocol] = __float2half_rn(tl[threadIdx.x][threadIdx.y]);
}

__global__ void zero_cnt_kernel(int* __restrict__ cnt) {
    cnt[threadIdx.x] = 0;
}

__global__ void copy4_kernel(const float4* __restrict__ src, float4* __restrict__ dst) {
    size_t i = (size_t)blockIdx.x * blockDim.x + threadIdx.x;
    dst[i] = src[i];
}

__global__ void passw_kernel(const float* __restrict__ reg_init,
                             const float* __restrict__ W,
                             const float* __restrict__ b,
                             float* __restrict__ pw) {
    __shared__ float red[256];
    int p = blockIdx.x;
    int tid = threadIdx.x;
    float acc = 0.f;
    for (int i = tid; i < PP * RDR; i += 256)
        acc += reg_init[i % RDR] * W[i * PP + p];
    red[tid] = acc; __syncthreads();
    #pragma unroll
    for (int o = 128; o > 0; o >>= 1) { if (tid < o) red[tid] += red[tid + o]; __syncthreads(); }
    if (tid == 0) pw[p] = 1.f / (1.f + expf(-(red[0] + b[p])));
}

__global__ void matvec_kernel(const float* __restrict__ M,
                              const float* __restrict__ v,
                              float* __restrict__ out) {
    __shared__ float red[128];
    int r = blockIdx.x;
    int tid = threadIdx.x;
    float acc = 0.f;
    #pragma unroll
    for (int j = tid; j < DD; j += 128)
        acc += M[(size_t)r * DD + j] * v[j];
    red[tid] = acc; __syncthreads();
    for (int o = 64; o > 0; o >>= 1) {
        if (tid < o) red[tid] += red[tid + o];
        __syncthreads();
    }
    if (tid == 0) out[r] = red[0];
}

__global__ void softmax_kernel(float* __restrict__ sc) {
    __shared__ float red[1024];
    int b = blockIdx.x;
    float* p = sc + (size_t)b * LL;
    int tid = threadIdx.x;
    float v0 = p[tid], v1 = p[tid + 1024];
    red[tid] = fmaxf(v0, v1); __syncthreads();
    #pragma unroll
    for (int o = 512; o > 0; o >>= 1) { if (tid < o) red[tid] = fmaxf(red[tid], red[tid + o]); __syncthreads(); }
    float mx = red[0];
    __syncthreads();
    float e0 = expf(v0 - mx), e1 = expf(v1 - mx);
    red[tid] = e0 + e1; __syncthreads();
    #pragma unroll
    for (int o = 512; o > 0; o >>= 1) { if (tid < o) red[tid] += red[tid + o]; __syncthreads(); }
    float inv = 1.f / red[0];
    p[tid] = e0 * inv;
    p[tid + 1024] = e1 * inv;
}

__global__ void wxpart_half_kernel(const float* __restrict__ a, const __half* __restrict__ xn,
                                   float* __restrict__ part) {
    int d = threadIdx.x;
    int blk = blockIdx.x;
    int row0 = blk * 64;
    float acc = 0.f;
    #pragma unroll 8
    for (int r = row0; r < row0 + 64; r++)
        acc += a[r] * __half2float(xn[(size_t)r * DD + d]);
    part[(size_t)blk * DD + d] = acc;
}

__global__ void part_reduce_kernel(const float* __restrict__ part, float* __restrict__ out,
                                   int nchunk, float scale) {
    int d = threadIdx.x;
    int g = blockIdx.x;
    const float* p = part + (size_t)g * nchunk * DD;
    float acc = 0.f;
    #pragma unroll 8
    for (int c = 0; c < nchunk; c++)
        acc += p[(size_t)c * DD + d];
    out[(size_t)g * DD + d] = acc * scale;
}

// ---------------- host orchestration ----------------

extern "C" void kernel_launch(void* const* d_in, const int* in_sizes, int n_in,
                              void* d_out, int out_size) {
    const float* x        = (const float*)d_in[0];
    const float* reg_init = (const float*)d_in[1];
    const float* ffn_ln_s = (const float*)d_in[2];
    const float* ffn_ln_b = (const float*)d_in[3];
    const float* ffn_w1   = (const float*)d_in[4];
    const float* ffn_b1   = (const float*)d_in[5];
    const float* ffn_w2   = (const float*)d_in[6];
    const float* ffn_b2   = (const float*)d_in[7];
    const float* gate_w   = (const float*)d_in[8];
    const float* gate_b   = (const float*)d_in[9];
    const float* wproj_w  = (const float*)d_in[10];
    const float* wgate_w  = (const float*)d_in[11];
    const float* wgate_b  = (const float*)d_in[12];
    const float* s4_q     = (const float*)d_in[13];
    const float* s4_k     = (const float*)d_in[14];
    const float* s4_v     = (const float*)d_in[15];
    const float* s4_sum   = (const float*)d_in[16];
    const float* s4_ln_s  = (const float*)d_in[17];
    const float* s4_ln_b  = (const float*)d_in[18];
    const float* ms3_w    = (const float*)d_in[19];
    const float* ms3_b    = (const float*)d_in[20];
    const float* m4_q     = (const float*)d_in[21];
    const float* m4_k     = (const float*)d_in[22];
    const float* m4_v     = (const float*)d_in[23];
    const float* m4_out   = (const float*)d_in[24];
    const float* m4_ln_s  = (const float*)d_in[25];
    const float* m4_ln_b  = (const float*)d_in[26];
    const float* out_ln_s = (const float*)d_in[27];
    const float* out_ln_b = (const float*)d_in[28];

    float *res, *delta, *sc, *part, *part1, *hsum, *q, *kq, *wxm, *summ, *gate;
    float *regsA, *regsB, *banks, *pw, *wxb, *ms1, *mo;
    int* cnt;
    __half *xnatt, *xnh, *hh, *w1th, *w2th;
    cudaGetSymbolAddress((void**)&res,   g_res);
    cudaGetSymbolAddress((void**)&delta, g_delta);
    cudaGetSymbolAddress((void**)&sc,    g_sc);
    cudaGetSymbolAddress((void**)&part,  g_part);
    cudaGetSymbolAddress((void**)&part1, g_part1);
    cudaGetSymbolAddress((void**)&hsum,  g_hsum);
    cudaGetSymbolAddress((void**)&q,     g_q);
    cudaGetSymbolAddress((void**)&kq,    g_kq);
    cudaGetSymbolAddress((void**)&wxm,   g_wxm);
    cudaGetSymbolAddress((void**)&summ,  g_summ);
    cudaGetSymbolAddress((void**)&gate,  g_gate);
    cudaGetSymbolAddress((void**)&regsA, g_regsA);
    cudaGetSymbolAddress((void**)&regsB, g_regsB);
    cudaGetSymbolAddress((void**)&banks, g_banks);
    cudaGetSymbolAddress((void**)&pw,    g_pw);
    cudaGetSymbolAddress((void**)&wxb,   g_wxb);
    cudaGetSymbolAddress((void**)&ms1,   g_ms1);
    cudaGetSymbolAddress((void**)&mo,    g_mo);
    cudaGetSymbolAddress((void**)&cnt,   g_cnt);
    cudaGetSymbolAddress((void**)&xnatt, g_xnatt);
    cudaGetSymbolAddress((void**)&xnh,   g_xnh);
    cudaGetSymbolAddress((void**)&hh,    g_hh);
    cudaGetSymbolAddress((void**)&w1th,  g_w1th);
    cudaGetSymbolAddress((void**)&w2th,  g_w2th);

    const int ELEM = NTOK * DD;

    // streams/events created once, outside capture
    static cudaStream_t sH = nullptr, sL = nullptr, sC = nullptr;
    static cudaEvent_t e0, eT, eG1, eG2, eCh, eLN, eEnd;
    if (!sH) {
        int lo, hi;
        cudaDeviceGetStreamPriorityRange(&lo, &hi);
        cudaStreamCreateWithPriority(&sH, cudaStreamNonBlocking, hi);   // spine: high
        cudaStreamCreateWithPriority(&sL, cudaStreamNonBlocking, lo);   // GEMM2: low
        cudaStreamCreateWithPriority(&sC, cudaStreamNonBlocking, lo);   // chains: low
        cudaEventCreateWithFlags(&e0,  cudaEventDisableTiming);
        cudaEventCreateWithFlags(&eT,  cudaEventDisableTiming);
        cudaEventCreateWithFlags(&eG1, cudaEventDisableTiming);
        cudaEventCreateWithFlags(&eG2, cudaEventDisableTiming);
        cudaEventCreateWithFlags(&eCh, cudaEventDisableTiming);
        cudaEventCreateWithFlags(&eLN, cudaEventDisableTiming);
        cudaEventCreateWithFlags(&eEnd, cudaEventDisableTiming);
    }

    cudaFuncSetAttribute(mmagemm_kernel<0>, cudaFuncAttributeMaxDynamicSharedMemorySize, NSTAGE * STAGE_BYTES);
    cudaFuncSetAttribute(mmagemm_kernel<1>, cudaFuncAttributeMaxDynamicSharedMemorySize, NSTAGE * STAGE_BYTES);

    // fork from origin stream
    cudaEventRecord(e0, 0);
    cudaStreamWaitEvent(sH, e0, 0);
    cudaStreamWaitEvent(sC, e0, 0);

    // prologue: transposes + counter zero on sC (feed GEMM1); prep chain on sH
    {
        dim3 blk(32, 32);
        transpose_all_kernel<<<6 * 768, blk, 0, sC>>>(ffn_w1, ffn_w2, w1th, w2th);
        zero_cnt_kernel<<<1, 64, 0, sC>>>(cnt);
        cudaEventRecord(eT, sC);
    }
    copy4_kernel<<<ELEM / 4 / 256, 256, 0, sH>>>((const float4*)x, (float4*)res);
    passw_kernel<<<PP, 256, 0, sH>>>(reg_init, ms3_w, ms3_b, pw);
    vecmat_split_kernel<<<8, 512, 0, sH>>>(banks, s4_q, nullptr, nullptr, q, 0, DD, 0);
    matvec_kernel<<<512, 128, 0, sH>>>(s4_k, q, kq);
    lnx_kernel<0,1,1><<<NTOK, 256, 0, sH>>>(res, nullptr, nullptr, nullptr, 0, nullptr,
                                            s4_ln_s, s4_ln_b, kq, sc, xnatt, nullptr,
                                            ffn_ln_s, ffn_ln_b, xnh);
    cudaEventRecord(eLN, sH);
    // pass-0 S4 chain on sC (after transposes; needs eLN data)
    cudaStreamWaitEvent(sC, eLN, 0);
    softmax_kernel<<<BB, 1024, 0, sC>>>(sc);
    wxpart_half_kernel<<<128, 512, 0, sC>>>(sc, xnatt, part);
    part_reduce_kernel<<<1, 512, 0, sC>>>(part, wxm, 128, 1.0f / BB);
    vecmat_split_kernel<<<8, 512, 0, sC>>>(wxm, s4_v, nullptr, nullptr, summ, DD, DD, 0);
    vecmat_split_kernel<<<12, 512, 0, sC>>>(summ, s4_sum, nullptr, reg_init, regsA, DD, RDR, 0);
    cudaStreamWaitEvent(sH, eT, 0);   // transposes + cnt zero before first GEMM1

    for (int p = 0; p < PP; p++) {
        float* regs_cur = regsA;
        float* regs_nxt = regsB;
        for (int ph = 0; ph < PHH; ph++) {
            const int pp = p * PHH + ph;
            const int gph = pp;                    // global phase 0..14
            {   // GEMM1 (sH): gelu + fp16 hh + part1 + row counters
                dim3 grid(FF / 128, NTOK / 128);
                mmagemm_kernel<1><<<grid, 256, NSTAGE * STAGE_BYTES, sH>>>(
                    xnh, w1th + (size_t)ph * FF * DD, ffn_b1 + (size_t)ph * FF,
                    hh, part1, nullptr, cnt, 0, NTOK, FF, DD);
            }
            cudaEventRecord(eG1, sH);
            // sL: GEMM2 launched immediately (spins on row counters), low priority
            cudaStreamWaitEvent(sL, eLN, 0);       // delta(t-1) consumed by LN(t-1)
            {
                dim3 grid(DD / 128, NTOK / 128);
                mmagemm_kernel<0><<<grid, 256, NSTAGE * STAGE_BYTES, sL>>>(
                    hh, w2th + (size_t)ph * DD * FF, ffn_b2 + (size_t)ph * DD,
                    nullptr, nullptr, delta, cnt, 12 * (gph + 1), NTOK, DD, FF);
            }
            cudaEventRecord(eG2, sL);
            // sC: summary/gate chain (needs full part1)
            cudaStreamWaitEvent(sC, eG1, 0);
            colsumH_kernel<<<3, 512, 0, sC>>>(part1, hsum);
            summk_kernel<<<512, 128, 0, sC>>>(hsum, w2th + (size_t)ph * DD * FF,
                                              ffn_b2 + (size_t)ph * DD, summ);
            gatereg_kernel<<<11, 512, 0, sC>>>(summ, regs_cur,
                                               gate_w + (size_t)pp * (RDR + DD) * DD,
                                               gate_b + (size_t)pp * DD, gate,
                                               wproj_w + (size_t)pp * RR * DD * DRR,
                                               wgate_w + (size_t)pp * RR * DD,
                                               wgate_b + (size_t)pp * RR,
                                               regs_nxt,
                                               (ph == PHH - 1) ? (banks + (size_t)p * RDR) : nullptr);
            if (ph == PHH - 1) {
                if (p < PP - 1) {
                    vecmat_split_kernel<<<8, 512, 0, sC>>>(banks, s4_q, nullptr, nullptr, q,
                                                           (p + 1) * RDR, DD, 0);
                    matvec_kernel<<<512, 128, 0, sC>>>(s4_k, q, kq);
                } else {
                    vecmat_split_kernel<<<8, 512, 0, sC>>>(banks, m4_q, nullptr, nullptr, q,
                                                           PP * RDR, DD, 0);
                    matvec_kernel<<<512, 128, 0, sC>>>(m4_k, q, kq);
                }
            }
            cudaEventRecord(eCh, sC);
            // sH: LN after GEMM2 + chain
            cudaStreamWaitEvent(sH, eG2, 0);
            cudaStreamWaitEvent(sH, eCh, 0);
            if (ph < PHH - 1) {
                lnx_kernel<1,0,1><<<NTOK, 256, 0, sH>>>(res, delta, gate, pw, p, nullptr,
                                                        nullptr, nullptr, nullptr, nullptr,
                                                        nullptr, nullptr,
                                                        ffn_ln_s + (size_t)(ph + 1) * DD,
                                                        ffn_ln_b + (size_t)(ph + 1) * DD, xnh);
            } else if (p < PP - 1) {
                lnx_kernel<1,1,1><<<NTOK, 256, 0, sH>>>(res, delta, gate, pw, p, nullptr,
                                                        s4_ln_s, s4_ln_b, kq, sc, xnatt, nullptr,
                                                        ffn_ln_s, ffn_ln_b, xnh);
            } else {
                lnx_kernel<1,1,0><<<NTOK, 256, 0, sH>>>(res, delta, gate, pw, p, nullptr,
                                                        m4_ln_s, m4_ln_b, kq, sc, xnatt, nullptr,
                                                        nullptr, nullptr, nullptr);
            }
            cudaEventRecord(eLN, sH);
            if (ph == PHH - 1 && p < PP - 1) {
                // next pass S4 chain on sC (overlaps next GEMM1)
                cudaStreamWaitEvent(sC, eLN, 0);
                softmax_kernel<<<BB, 1024, 0, sC>>>(sc);
                wxpart_half_kernel<<<128, 512, 0, sC>>>(sc, xnatt, part);
                part_reduce_kernel<<<1, 512, 0, sC>>>(part, wxm, 128, 1.0f / BB);
                vecmat_split_kernel<<<8, 512, 0, sC>>>(wxm, s4_v, nullptr, nullptr, summ, DD, DD, 0);
                vecmat_split_kernel<<<12, 512, 0, sC>>>(summ, s4_sum, nullptr, reg_init, regsA, DD, RDR, 0);
            }
            float* tmp = regs_cur; regs_cur = regs_nxt; regs_nxt = tmp;
        }
    }

    // ---- MetaS4 (sH) ----
    softmax_kernel<<<BB, 1024, 0, sH>>>(sc);
    wxpart_half_kernel<<<128, 512, 0, sH>>>(sc, xnatt, part);
    part_reduce_kernel<<<BB, 512, 0, sH>>>(part, wxb, 32, 1.0f);
    {
        dim3 g(8, BB);
        vecmat_b4_kernel<<<g, 512, 0, sH>>>(wxb, m4_v, ms1);
        vecmat_b4_kernel<<<g, 512, 0, sH>>>(ms1, m4_out, mo);
    }
    lnx_kernel<2,2,0><<<NTOK, 256, 0, sH>>>(res, nullptr, nullptr, nullptr, 0, mo,
                                            out_ln_s, out_ln_b, nullptr, nullptr,
                                            nullptr, (float*)d_out, nullptr, nullptr, nullptr);
    // join back to origin stream
    cudaEventRecord(eEnd, sH);
    cudaStreamWaitEvent(0, eEnd, 0);
}

// round 12
// speedup vs baseline: 1.0494x; 1.0494x over previous
#include <cuda_runtime.h>
#include <cuda_fp16.h>
#include <math.h>
#include <stdint.h>

// ---------------- problem constants ----------------
#define BB 4
#define LL 2048
#define DD 512
#define DRR 256
#define RR 3
#define PP 5
#define PHH 3
#define FF 1536
#define NTOK (BB*LL)            // 8192
#define RDR (RR*DRR)            // 768

// ---------------- device scratch ----------------
__device__ __align__(256) float g_res[NTOK*DD];
__device__ __align__(256) float g_delta[NTOK*DD];
__device__ __align__(256) float g_sc[NTOK];
__device__ __align__(256) float g_part[128*DD];
__device__ __align__(256) float g_part1[64*FF];
__device__ __align__(256) float g_hsum[FF];
__device__ __align__(256) float g_q[DD];
__device__ __align__(256) float g_kq[DD];
__device__ __align__(256) float g_wxm[DD];
__device__ __align__(256) float g_summ[DD];
__device__ __align__(256) float g_regsA[RDR];
__device__ __align__(256) float g_regsB[RDR];
__device__ __align__(256) float g_gate[DD];
__device__ __align__(256) float g_banks[PP*RDR];
__device__ __align__(256) float g_pw[16];
__device__ __align__(256) float g_wxb[BB*DD];
__device__ __align__(256) float g_ms1[BB*DD];
__device__ __align__(256) float g_mo[BB*DD];

__device__ __align__(256) __half g_xnatt[NTOK*DD];
__device__ __align__(256) __half g_xnh[NTOK*DD];
__device__ __align__(256) __half g_hh[NTOK*FF];
__device__ __align__(256) __half g_w1th[PHH*FF*DD];
__device__ __align__(256) __half g_w2th[PHH*DD*FF];

// ---------------- PTX helpers ----------------
__device__ __forceinline__ uint32_t smem_u32(const void* p) {
    return (uint32_t)__cvta_generic_to_shared(p);
}
__device__ __forceinline__ void cpasync16(uint32_t dst, const void* src) {
    asm volatile("cp.async.cg.shared.global [%0], [%1], 16;" :: "r"(dst), "l"(src) : "memory");
}
__device__ __forceinline__ void cp_commit() {
    asm volatile("cp.async.commit_group;" ::: "memory");
}
__device__ __forceinline__ void cp_wait1() {
    asm volatile("cp.async.wait_group 1;" ::: "memory");
}
__device__ __forceinline__ void ldsm4(uint32_t* r, uint32_t addr) {
    asm volatile("ldmatrix.sync.aligned.m8n8.x4.shared.b16 {%0,%1,%2,%3}, [%4];"
                 : "=r"(r[0]), "=r"(r[1]), "=r"(r[2]), "=r"(r[3]) : "r"(addr));
}
__device__ __forceinline__ void mma16816(float* c, const uint32_t* a, uint32_t b0, uint32_t b1) {
    asm volatile(
        "mma.sync.aligned.m16n8k16.row.col.f32.f16.f16.f32 "
        "{%0,%1,%2,%3}, {%4,%5,%6,%7}, {%8,%9}, {%0,%1,%2,%3};"
        : "+f"(c[0]), "+f"(c[1]), "+f"(c[2]), "+f"(c[3])
        : "r"(a[0]), "r"(a[1]), "r"(a[2]), "r"(a[3]), "r"(b0), "r"(b1));
}

// ---------------- fp16 GEMM via mma.sync ----------------
// MODE 1 (GEMM1): Ch = fp16(gelu(acc+bias)); part1[by*1536+col] = per-CTA colsum of gelu.
// MODE 0 (GEMM2): Cf = acc + bias (delta).
#define STAGE_BYTES 32768
#define NSTAGE 3

template <int OUTMODE>
__global__ void __launch_bounds__(256, 2)
mmagemm_kernel(const __half* __restrict__ Ah, const __half* __restrict__ Bh,
               const float* __restrict__ bias,
               __half* __restrict__ Ch, float* __restrict__ part1,
               float* __restrict__ Cf,
               int M, int N, int K) {
    extern __shared__ __align__(128) unsigned char smem[];

    const int tid  = threadIdx.x;
    const int wid  = tid >> 5;
    const int lane = tid & 31;
    const int n0 = blockIdx.x * 128;
    const int m0 = blockIdx.y * 128;
    const int NIT = K >> 6;
    const uint32_t smem_base = smem_u32(smem);

    int lrowA[4]; int lcA[4]; uint32_t ldst[4];
    #pragma unroll
    for (int u = 0; u < 4; u++) {
        int s = tid + u * 256;
        int row = s >> 3, c = s & 7;
        lrowA[u] = row; lcA[u] = c;
        ldst[u] = (uint32_t)(row * 128 + ((c ^ (row & 7)) << 4));
    }

    auto prefetch = [&](int it) {
        const int k0 = it << 6;
        const uint32_t st = smem_base + (uint32_t)(it % NSTAGE) * STAGE_BYTES;
        #pragma unroll
        for (int u = 0; u < 4; u++)
            cpasync16(st + ldst[u], Ah + (size_t)(m0 + lrowA[u]) * K + k0 + lcA[u] * 8);
        #pragma unroll
        for (int u = 0; u < 4; u++)
            cpasync16(st + 16384 + ldst[u], Bh + (size_t)(n0 + lrowA[u]) * K + k0 + lcA[u] * 8);
        cp_commit();
    };

    float acc[2][8][4];
    #pragma unroll
    for (int i = 0; i < 2; i++)
        #pragma unroll
        for (int j = 0; j < 8; j++)
            #pragma unroll
            for (int t = 0; t < 4; t++) acc[i][j][t] = 0.f;

    const int wm = (wid & 3) * 32;
    const int wn = (wid >> 2) * 64;
    const int lrow = lane & 15;
    const int lseg = lane >> 4;

    prefetch(0);
    if (NIT > 1) prefetch(1);

    #pragma unroll 1
    for (int it = 0; it < NIT; it++) {
        cp_wait1();
        __syncthreads();
        if (it + 2 < NIT) prefetch(it + 2);

        const uint32_t st = smem_base + (uint32_t)(it % NSTAGE) * STAGE_BYTES;
        #pragma unroll
        for (int kk = 0; kk < 4; kk++) {
            uint32_t af[2][4];
            #pragma unroll
            for (int i = 0; i < 2; i++) {
                int row = wm + i * 16 + lrow;
                int seg = kk * 2 + lseg;
                ldsm4(af[i], st + (uint32_t)(row * 128 + (((seg ^ (row & 7))) << 4)));
            }
            uint32_t bf[4][4];
            #pragma unroll
            for (int g = 0; g < 4; g++) {
                int row = wn + g * 16 + lrow;
                int seg = kk * 2 + lseg;
                ldsm4(bf[g], st + 16384u + (uint32_t)(row * 128 + (((seg ^ (row & 7))) << 4)));
            }
            #pragma unroll
            for (int i = 0; i < 2; i++)
                #pragma unroll
                for (int j = 0; j < 8; j++) {
                    int g = j >> 1, w = j & 1;
                    mma16816(acc[i][j], af[i], bf[g][w], bf[g][w + 2]);
                }
        }
    }

    const int l4 = lane >> 2;
    const int l2 = (lane & 3) * 2;

    if (OUTMODE == 1) {
        float vg[2][8][4];
        #pragma unroll
        for (int i = 0; i < 2; i++)
            #pragma unroll
            for (int j = 0; j < 8; j++) {
                const int col = n0 + wn + j * 8 + l2;
                const float b0v = bias[col], b1v = bias[col + 1];
                float t0 = acc[i][j][0] + b0v, t1 = acc[i][j][1] + b1v;
                float t2 = acc[i][j][2] + b0v, t3 = acc[i][j][3] + b1v;
                vg[i][j][0] = 0.5f * t0 * (1.0f + erff(t0 * 0.70710678118654752f));
                vg[i][j][1] = 0.5f * t1 * (1.0f + erff(t1 * 0.70710678118654752f));
                vg[i][j][2] = 0.5f * t2 * (1.0f + erff(t2 * 0.70710678118654752f));
                vg[i][j][3] = 0.5f * t3 * (1.0f + erff(t3 * 0.70710678118654752f));
            }
        float cs0[8], cs1[8];
        #pragma unroll
        for (int j = 0; j < 8; j++) {
            cs0[j] = vg[0][j][0] + vg[0][j][2] + vg[1][j][0] + vg[1][j][2];
            cs1[j] = vg[0][j][1] + vg[0][j][3] + vg[1][j][1] + vg[1][j][3];
            #pragma unroll
            for (int off = 4; off <= 16; off <<= 1) {
                cs0[j] += __shfl_xor_sync(0xffffffffu, cs0[j], off);
                cs1[j] += __shfl_xor_sync(0xffffffffu, cs1[j], off);
            }
        }
        __syncthreads();
        float* cs = (float*)smem;
        if (lane < 4) {
            #pragma unroll
            for (int j = 0; j < 8; j++) {
                cs[wid * 64 + j * 8 + lane * 2 + 0] = cs0[j];
                cs[wid * 64 + j * 8 + lane * 2 + 1] = cs1[j];
            }
        }
        __syncthreads();
        if (tid < 128) {
            int ng = tid >> 6, cw = tid & 63;
            float s = cs[(ng * 4 + 0) * 64 + cw] + cs[(ng * 4 + 1) * 64 + cw]
                    + cs[(ng * 4 + 2) * 64 + cw] + cs[(ng * 4 + 3) * 64 + cw];
            part1[(size_t)blockIdx.y * FF + n0 + ng * 64 + cw] = s;
        }
        #pragma unroll
        for (int i = 0; i < 2; i++)
            #pragma unroll
            for (int j = 0; j < 8; j++) {
                const int col = n0 + wn + j * 8 + l2;
                const int row0 = m0 + wm + i * 16 + l4;
                unsigned short h0 = __half_as_ushort(__float2half_rn(vg[i][j][0]));
                unsigned short h1 = __half_as_ushort(__float2half_rn(vg[i][j][1]));
                unsigned short h2 = __half_as_ushort(__float2half_rn(vg[i][j][2]));
                unsigned short h3 = __half_as_ushort(__float2half_rn(vg[i][j][3]));
                *(ushort2*)((unsigned short*)Ch + (size_t)row0 * N + col)       = make_ushort2(h0, h1);
                *(ushort2*)((unsigned short*)Ch + (size_t)(row0 + 8) * N + col) = make_ushort2(h2, h3);
            }
    } else {
        #pragma unroll
        for (int i = 0; i < 2; i++)
            #pragma unroll
            for (int j = 0; j < 8; j++) {
                const int col = n0 + wn + j * 8 + l2;
                const int row0 = m0 + wm + i * 16 + l4;
                const float b0v = bias[col], b1v = bias[col + 1];
                *(float2*)(Cf + (size_t)row0 * N + col) =
                    make_float2(acc[i][j][0] + b0v, acc[i][j][1] + b1v);
                *(float2*)(Cf + (size_t)(row0 + 8) * N + col) =
                    make_float2(acc[i][j][2] + b0v, acc[i][j][3] + b1v);
            }
    }
}

// ---------------- fused residual-update + LayerNorm ----------------
template <int INMODE, int XNMODE, int EMIT_XNH>
__global__ void lnx_kernel(float* __restrict__ res,
                           const float* __restrict__ delta, const float* __restrict__ gate,
                           const float* __restrict__ pw, int p,
                           const float* __restrict__ mo,
                           const float* __restrict__ sA, const float* __restrict__ bA,
                           const float* __restrict__ kq, float* __restrict__ score,
                           __half* __restrict__ xn, float* __restrict__ outf,
                           const float* __restrict__ sB, const float* __restrict__ bB,
                           __half* __restrict__ xnh) {
    __shared__ float red[256];
    int t = blockIdx.x;
    int tid = threadIdx.x;
    float2 v = ((const float2*)res)[(size_t)t * 256 + tid];
    if (INMODE == 1) {
        float w = pw[p];
        float2 d = ((const float2*)delta)[(size_t)t * 256 + tid];
        float2 g = ((const float2*)gate)[tid];
        v.x += w * g.x * d.x;
        v.y += w * g.y * d.y;
        ((float2*)res)[(size_t)t * 256 + tid] = v;
    } else if (INMODE == 2) {
        int b = t >> 11;
        float2 m = ((const float2*)mo)[(b << 8) + tid];
        v.x += m.x; v.y += m.y;
    }
    red[tid] = v.x + v.y; __syncthreads();
    #pragma unroll
    for (int o = 128; o > 0; o >>= 1) { if (tid < o) red[tid] += red[tid + o]; __syncthreads(); }
    float mean = red[0] * (1.0f / 512.0f);
    __syncthreads();
    float d0 = v.x - mean, d1 = v.y - mean;
    red[tid] = d0 * d0 + d1 * d1; __syncthreads();
    #pragma unroll
    for (int o = 128; o > 0; o >>= 1) { if (tid < o) red[tid] += red[tid + o]; __syncthreads(); }
    float rstd = rsqrtf(red[0] * (1.0f / 512.0f) + 1e-5f);
    __syncthreads();
    if (XNMODE) {
        float2 s = ((const float2*)sA)[tid];
        float2 b = ((const float2*)bA)[tid];
        float y0 = d0 * rstd * s.x + b.x;
        float y1 = d1 * rstd * s.y + b.y;
        if (XNMODE == 1) {
            ((__half2*)xn)[(size_t)t * 256 + tid] =
                __halves2half2(__float2half_rn(y0), __float2half_rn(y1));
            float2 k = ((const float2*)kq)[tid];
            red[tid] = y0 * k.x + y1 * k.y; __syncthreads();
            #pragma unroll
            for (int o = 128; o > 0; o >>= 1) { if (tid < o) red[tid] += red[tid + o]; __syncthreads(); }
            if (tid == 0) score[t] = red[0] * 0.044194173824159216f;
        } else {
            ((float2*)outf)[(size_t)t * 256 + tid] = make_float2(y0, y1);
        }
    }
    if (EMIT_XNH) {
        float2 s = ((const float2*)sB)[tid];
        float2 b = ((const float2*)bB)[tid];
        float z0 = d0 * rstd * s.x + b.x;
        float z1 = d1 * rstd * s.y + b.y;
        ((__half2*)xnh)[(size_t)t * 256 + tid] =
            __halves2half2(__float2half_rn(z0), __float2half_rn(z1));
    }
}

// ---------------- hsum: column sums of part1 (64 x 1536) ----------------
__global__ void colsumH_kernel(const float* __restrict__ part1, float* __restrict__ hsum) {
    int col = blockIdx.x * 512 + threadIdx.x;
    float acc = 0.f;
    #pragma unroll 8
    for (int c = 0; c < 64; c++)
        acc += part1[(size_t)c * FF + col];
    hsum[col] = acc;
}

// ---------------- summary: summ[j] = hsum@w2[:,j]/NTOK + b2[j] ----------------
__global__ void summk_kernel(const float* __restrict__ hsum, const __half* __restrict__ w2t,
                             const float* __restrict__ b2, float* __restrict__ summ) {
    __shared__ float red[128];
    int j = blockIdx.x;
    int tid = threadIdx.x;
    const __half* row = w2t + (size_t)j * FF;
    float acc = 0.f;
    #pragma unroll
    for (int k = tid; k < FF; k += 128)
        acc += hsum[k] * __half2float(row[k]);
    red[tid] = acc; __syncthreads();
    #pragma unroll
    for (int o = 64; o > 0; o >>= 1) { if (tid < o) red[tid] += red[tid + o]; __syncthreads(); }
    if (tid == 0) summ[j] = red[0] * (1.0f / (float)NTOK) + b2[j];
}

// ---------------- gate + register update (11 blocks x 512) ----------------
__global__ void gatereg_kernel(const float* __restrict__ summ, const float* __restrict__ regs_cur,
                               const float* __restrict__ gM, const float* __restrict__ gb,
                               float* __restrict__ gate,
                               const float* __restrict__ Wp, const float* __restrict__ Wg,
                               const float* __restrict__ bg,
                               float* __restrict__ regs_next, float* __restrict__ banks) {
    __shared__ float red[512];
    int tid = threadIdx.x;
    if (blockIdx.x < 8) {
        int j = blockIdx.x * 64 + (tid & 63);
        int s = tid >> 6;
        float a = 0.f;
        #pragma unroll 8
        for (int d = s * 160; d < s * 160 + 160; d++) {
            float v = (d < RDR) ? regs_cur[d] : summ[d - RDR];
            a += v * gM[(size_t)d * DD + j];
        }
        red[tid] = a; __syncthreads();
        if (tid < 64) {
            float g = 0.f;
            #pragma unroll
            for (int k = 0; k < 8; k++) g += red[k * 64 + tid];
            g += gb[j];
            gate[j] = 1.f / (1.f + expf(-g));
        }
    } else {
        __shared__ float shw;
        int r = blockIdx.x - 8;
        red[tid] = summ[tid] * Wg[(size_t)r * DD + tid];
        __syncthreads();
        #pragma unroll
        for (int o = 256; o > 0; o >>= 1) { if (tid < o) red[tid] += red[tid + o]; __syncthreads(); }
        if (tid == 0) shw = 1.f / (1.f + expf(-(red[0] + bg[r])));
        __syncthreads();
        int k = tid & 255, s = tid >> 8;
        const float* W = Wp + (size_t)r * DD * DRR;
        float a = 0.f;
        #pragma unroll 16
        for (int d = s * 256; d < (s + 1) * 256; d++)
            a += summ[d] * W[(size_t)d * DRR + k];
        red[tid] = a; __syncthreads();
        if (tid < 256) {
            float nv = regs_cur[r * DRR + k] + shw * (red[k] + red[k + 256]);
            regs_next[r * DRR + k] = nv;
            if (banks) banks[r * DRR + k] = nv;
        }
    }
}

// ---------------- k-split vec @ mat (fp32) ----------------
__global__ void vecmat_split_kernel(const float* __restrict__ v, const float* __restrict__ M,
                                    const float* __restrict__ bias, const float* __restrict__ init,
                                    float* __restrict__ out, int nrow, int ncol, int act) {
    __shared__ float red[512];
    int tid = threadIdx.x;
    int j = blockIdx.x * 64 + (tid & 63);
    int s = tid >> 6;
    int sl = nrow >> 3;
    float acc = 0.f;
    #pragma unroll 16
    for (int d = s * sl; d < (s + 1) * sl; d++)
        acc += v[d] * M[(size_t)d * ncol + j];
    red[tid] = acc; __syncthreads();
    if (tid < 64) {
        float a = 0.f;
        #pragma unroll
        for (int k = 0; k < 8; k++) a += red[k * 64 + tid];
        if (bias) a += bias[j];
        if (init) a += init[j];
        if (act == 1) a = 1.f / (1.f + expf(-a));
        out[j] = a;
    }
}

// batched (4x) 512x512 vec@mat: out[b*512+j] = v[b*512+:] @ M
__global__ void vecmat_b4_kernel(const float* __restrict__ v, const float* __restrict__ M,
                                 float* __restrict__ out) {
    __shared__ float red[512];
    int tid = threadIdx.x;
    int b = blockIdx.y;
    int j = blockIdx.x * 64 + (tid & 63);
    int s = tid >> 6;
    const float* vb = v + (size_t)b * DD;
    float acc = 0.f;
    #pragma unroll 16
    for (int d = s * 64; d < (s + 1) * 64; d++)
        acc += vb[d] * M[(size_t)d * DD + j];
    red[tid] = acc; __syncthreads();
    if (tid < 64) {
        float a = 0.f;
        #pragma unroll
        for (int k = 0; k < 8; k++) a += red[k * 64 + tid];
        out[(size_t)b * DD + j] = a;
    }
}

// ---------------- other small kernels ----------------

__global__ void transpose_all_kernel(const float* __restrict__ w1, const float* __restrict__ w2,
                                     __half* __restrict__ w1t, __half* __restrict__ w2t) {
    __shared__ float tl[32][33];
    int bid = blockIdx.x;
    int m = bid / 768;
    int t = bid % 768;
    const float* src; __half* dst; int R, C;
    if (m < 3) { src = w1 + (size_t)m * DD * FF; dst = w1t + (size_t)m * FF * DD; R = DD; C = FF; }
    else { int ph = m - 3; src = w2 + (size_t)ph * FF * DD; dst = w2t + (size_t)ph * DD * FF; R = FF; C = DD; }
    int tpr = C >> 5;
    int ty = t / tpr, tx = t % tpr;
    int r = ty * 32 + threadIdx.y, c = tx * 32 + threadIdx.x;
    tl[threadIdx.y][threadIdx.x] = src[(size_t)r * C + c];
    __syncthreads();
    int orow = tx * 32 + threadIdx.y, ocol = ty * 32 + threadIdx.x;
    dst[(size_t)orow * R + ocol] = __float2half_rn(tl[threadIdx.x][threadIdx.y]);
}

__global__ void copy4_kernel(const float4* __restrict__ src, float4* __restrict__ dst) {
    size_t i = (size_t)blockIdx.x * blockDim.x + threadIdx.x;
    dst[i] = src[i];
}

__global__ void passw_kernel(const float* __restrict__ reg_init,
                             const float* __restrict__ W,
                             const float* __restrict__ b,
                             float* __restrict__ pw) {
    __shared__ float red[256];
    int p = blockIdx.x;
    int tid = threadIdx.x;
    float acc = 0.f;
    for (int i = tid; i < PP * RDR; i += 256)
        acc += reg_init[i % RDR] * W[i * PP + p];
    red[tid] = acc; __syncthreads();
    #pragma unroll
    for (int o = 128; o > 0; o >>= 1) { if (tid < o) red[tid] += red[tid + o]; __syncthreads(); }
    if (tid == 0) pw[p] = 1.f / (1.f + expf(-(red[0] + b[p])));
}

__global__ void matvec_kernel(const float* __restrict__ M,
                              const float* __restrict__ v,
                              float* __restrict__ out) {
    __shared__ float red[128];
    int r = blockIdx.x;
    int tid = threadIdx.x;
    float acc = 0.f;
    #pragma unroll
    for (int j = tid; j < DD; j += 128)
        acc += M[(size_t)r * DD + j] * v[j];
    red[tid] = acc; __syncthreads();
    for (int o = 64; o > 0; o >>= 1) {
        if (tid < o) red[tid] += red[tid + o];
        __syncthreads();
    }
    if (tid == 0) out[r] = red[0];
}

__global__ void softmax_kernel(float* __restrict__ sc) {
    __shared__ float red[1024];
    int b = blockIdx.x;
    float* p = sc + (size_t)b * LL;
    int tid = threadIdx.x;
    float v0 = p[tid], v1 = p[tid + 1024];
    red[tid] = fmaxf(v0, v1); __syncthreads();
    #pragma unroll
    for (int o = 512; o > 0; o >>= 1) { if (tid < o) red[tid] = fmaxf(red[tid], red[tid + o]); __syncthreads(); }
    float mx = red[0];
    __syncthreads();
    float e0 = expf(v0 - mx), e1 = expf(v1 - mx);
    red[tid] = e0 + e1; __syncthreads();
    #pragma unroll
    for (int o = 512; o > 0; o >>= 1) { if (tid < o) red[tid] += red[tid + o]; __syncthreads(); }
    float inv = 1.f / red[0];
    p[tid] = e0 * inv;
    p[tid + 1024] = e1 * inv;
}

__global__ void wxpart_half_kernel(const float* __restrict__ a, const __half* __restrict__ xn,
                                   float* __restrict__ part) {
    int d = threadIdx.x;
    int blk = blockIdx.x;
    int row0 = blk * 64;
    float acc = 0.f;
    #pragma unroll 8
    for (int r = row0; r < row0 + 64; r++)
        acc += a[r] * __half2float(xn[(size_t)r * DD + d]);
    part[(size_t)blk * DD + d] = acc;
}

__global__ void part_reduce_kernel(const float* __restrict__ part, float* __restrict__ out,
                                   int nchunk, float scale) {
    int d = threadIdx.x;
    int g = blockIdx.x;
    const float* p = part + (size_t)g * nchunk * DD;
    float acc = 0.f;
    #pragma unroll 8
    for (int c = 0; c < nchunk; c++)
        acc += p[(size_t)c * DD + d];
    out[(size_t)g * DD + d] = acc * scale;
}

// ---------------- host orchestration ----------------

extern "C" void kernel_launch(void* const* d_in, const int* in_sizes, int n_in,
                              void* d_out, int out_size) {
    const float* x        = (const float*)d_in[0];
    const float* reg_init = (const float*)d_in[1];
    const float* ffn_ln_s = (const float*)d_in[2];
    const float* ffn_ln_b = (const float*)d_in[3];
    const float* ffn_w1   = (const float*)d_in[4];
    const float* ffn_b1   = (const float*)d_in[5];
    const float* ffn_w2   = (const float*)d_in[6];
    const float* ffn_b2   = (const float*)d_in[7];
    const float* gate_w   = (const float*)d_in[8];
    const float* gate_b   = (const float*)d_in[9];
    const float* wproj_w  = (const float*)d_in[10];
    const float* wgate_w  = (const float*)d_in[11];
    const float* wgate_b  = (const float*)d_in[12];
    const float* s4_q     = (const float*)d_in[13];
    const float* s4_k     = (const float*)d_in[14];
    const float* s4_v     = (const float*)d_in[15];
    const float* s4_sum   = (const float*)d_in[16];
    const float* s4_ln_s  = (const float*)d_in[17];
    const float* s4_ln_b  = (const float*)d_in[18];
    const float* ms3_w    = (const float*)d_in[19];
    const float* ms3_b    = (const float*)d_in[20];
    const float* m4_q     = (const float*)d_in[21];
    const float* m4_k     = (const float*)d_in[22];
    const float* m4_v     = (const float*)d_in[23];
    const float* m4_out   = (const float*)d_in[24];
    const float* m4_ln_s  = (const float*)d_in[25];
    const float* m4_ln_b  = (const float*)d_in[26];
    const float* out_ln_s = (const float*)d_in[27];
    const float* out_ln_b = (const float*)d_in[28];

    float *res, *delta, *sc, *part, *part1, *hsum, *q, *kq, *wxm, *summ, *gate;
    float *regsA, *regsB, *banks, *pw, *wxb, *ms1, *mo;
    __half *xnatt, *xnh, *hh, *w1th, *w2th;
    cudaGetSymbolAddress((void**)&res,   g_res);
    cudaGetSymbolAddress((void**)&delta, g_delta);
    cudaGetSymbolAddress((void**)&sc,    g_sc);
    cudaGetSymbolAddress((void**)&part,  g_part);
    cudaGetSymbolAddress((void**)&part1, g_part1);
    cudaGetSymbolAddress((void**)&hsum,  g_hsum);
    cudaGetSymbolAddress((void**)&q,     g_q);
    cudaGetSymbolAddress((void**)&kq,    g_kq);
    cudaGetSymbolAddress((void**)&wxm,   g_wxm);
    cudaGetSymbolAddress((void**)&summ,  g_summ);
    cudaGetSymbolAddress((void**)&gate,  g_gate);
    cudaGetSymbolAddress((void**)&regsA, g_regsA);
    cudaGetSymbolAddress((void**)&regsB, g_regsB);
    cudaGetSymbolAddress((void**)&banks, g_banks);
    cudaGetSymbolAddress((void**)&pw,    g_pw);
    cudaGetSymbolAddress((void**)&wxb,   g_wxb);
    cudaGetSymbolAddress((void**)&ms1,   g_ms1);
    cudaGetSymbolAddress((void**)&mo,    g_mo);
    cudaGetSymbolAddress((void**)&xnatt, g_xnatt);
    cudaGetSymbolAddress((void**)&xnh,   g_xnh);
    cudaGetSymbolAddress((void**)&hh,    g_hh);
    cudaGetSymbolAddress((void**)&w1th,  g_w1th);
    cudaGetSymbolAddress((void**)&w2th,  g_w2th);

    const int ELEM = NTOK * DD;

    // side stream + events (created once, outside capture)
    static cudaStream_t s2 = nullptr;
    static cudaEvent_t e0 = nullptr, eT = nullptr, evG1 = nullptr, evS2 = nullptr, evLN = nullptr;
    if (!s2) {
        cudaStreamCreateWithFlags(&s2, cudaStreamNonBlocking);
        cudaEventCreateWithFlags(&e0,  cudaEventDisableTiming);
        cudaEventCreateWithFlags(&eT,  cudaEventDisableTiming);
        cudaEventCreateWithFlags(&evG1, cudaEventDisableTiming);
        cudaEventCreateWithFlags(&evS2, cudaEventDisableTiming);
        cudaEventCreateWithFlags(&evLN, cudaEventDisableTiming);
    }

    cudaFuncSetAttribute(mmagemm_kernel<0>, cudaFuncAttributeMaxDynamicSharedMemorySize, NSTAGE * STAGE_BYTES);
    cudaFuncSetAttribute(mmagemm_kernel<1>, cudaFuncAttributeMaxDynamicSharedMemorySize, NSTAGE * STAGE_BYTES);

    // fork: transposes + passw on s2 overlap the main-stream prologue
    cudaEventRecord(e0, 0);
    cudaStreamWaitEvent(s2, e0, 0);
    {
        dim3 blk(32, 32);
        transpose_all_kernel<<<6 * 768, blk, 0, s2>>>(ffn_w1, ffn_w2, w1th, w2th);
        passw_kernel<<<PP, 256, 0, s2>>>(reg_init, ms3_w, ms3_b, pw);
        cudaEventRecord(eT, s2);
    }
    copy4_kernel<<<ELEM / 4 / 256, 256>>>((const float4*)x, (float4*)res);
    vecmat_split_kernel<<<8, 512>>>(banks, s4_q, nullptr, nullptr, q, 0, DD, 0);
    matvec_kernel<<<512, 128>>>(s4_k, q, kq);
    lnx_kernel<0,1,1><<<NTOK, 256>>>(res, nullptr, nullptr, nullptr, 0, nullptr,
                                     s4_ln_s, s4_ln_b, kq, sc, xnatt, nullptr,
                                     ffn_ln_s, ffn_ln_b, xnh);
    softmax_kernel<<<BB, 1024>>>(sc);
    wxpart_half_kernel<<<128, 512>>>(sc, xnatt, part);
    part_reduce_kernel<<<1, 512>>>(part, wxm, 128, 1.0f / BB);
    vecmat_split_kernel<<<8, 512>>>(wxm, s4_v, nullptr, nullptr, summ, DD, DD, 0);
    vecmat_split_kernel<<<12, 512>>>(summ, s4_sum, nullptr, reg_init, regsA, DD, RDR, 0);
    cudaStreamWaitEvent(0, eT, 0);   // transposes+pw ready before first GEMM1 / LN use

    for (int p = 0; p < PP; p++) {
        float* regs_cur = regsA;
        float* regs_nxt = regsB;
        for (int ph = 0; ph < PHH; ph++) {
            const int pp = p * PHH + ph;
            {   // GEMM1 (main): gelu + fp16 hh + part1 column sums
                dim3 grid(FF / 128, NTOK / 128);
                mmagemm_kernel<1><<<grid, 256, NSTAGE * STAGE_BYTES>>>(
                    xnh, w1th + (size_t)ph * FF * DD, ffn_b1 + (size_t)ph * FF,
                    hh, part1, nullptr, NTOK, FF, DD);
            }
            cudaEventRecord(evG1, 0);
            cudaStreamWaitEvent(s2, evG1, 0);
            // s2: summary chain (overlaps GEMM2 on main)
            colsumH_kernel<<<3, 512, 0, s2>>>(part1, hsum);
            summk_kernel<<<512, 128, 0, s2>>>(hsum, w2th + (size_t)ph * DD * FF,
                                              ffn_b2 + (size_t)ph * DD, summ);
            gatereg_kernel<<<11, 512, 0, s2>>>(summ, regs_cur,
                                               gate_w + (size_t)pp * (RDR + DD) * DD,
                                               gate_b + (size_t)pp * DD, gate,
                                               wproj_w + (size_t)pp * RR * DD * DRR,
                                               wgate_w + (size_t)pp * RR * DD,
                                               wgate_b + (size_t)pp * RR,
                                               regs_nxt,
                                               (ph == PHH - 1) ? (banks + (size_t)p * RDR) : nullptr);
            if (ph == PHH - 1) {
                // kq chain for next pass / MetaS4 (s2)
                if (p < PP - 1) {
                    vecmat_split_kernel<<<8, 512, 0, s2>>>(banks, s4_q, nullptr, nullptr, q,
                                                           (p + 1) * RDR, DD, 0);
                    matvec_kernel<<<512, 128, 0, s2>>>(s4_k, q, kq);
                } else {
                    vecmat_split_kernel<<<8, 512, 0, s2>>>(banks, m4_q, nullptr, nullptr, q,
                                                           PP * RDR, DD, 0);
                    matvec_kernel<<<512, 128, 0, s2>>>(m4_k, q, kq);
                }
            }
            cudaEventRecord(evS2, s2);
            {   // GEMM2 (main): delta = acc + b2  (independent of gate)
                dim3 grid(DD / 128, NTOK / 128);
                mmagemm_kernel<0><<<grid, 256, NSTAGE * STAGE_BYTES>>>(
                    hh, w2th + (size_t)ph * DD * FF, ffn_b2 + (size_t)ph * DD,
                    nullptr, nullptr, delta, NTOK, DD, FF);
            }
            cudaStreamWaitEvent(0, evS2, 0);
            // LN (main): res += pw*gate*delta, emit next inputs
            if (ph < PHH - 1) {
                lnx_kernel<1,0,1><<<NTOK, 256>>>(res, delta, gate, pw, p, nullptr,
                                                 nullptr, nullptr, nullptr, nullptr,
                                                 nullptr, nullptr,
                                                 ffn_ln_s + (size_t)(ph + 1) * DD,
                                                 ffn_ln_b + (size_t)(ph + 1) * DD, xnh);
            } else if (p < PP - 1) {
                lnx_kernel<1,1,1><<<NTOK, 256>>>(res, delta, gate, pw, p, nullptr,
                                                 s4_ln_s, s4_ln_b, kq, sc, xnatt, nullptr,
                                                 ffn_ln_s, ffn_ln_b, xnh);
                cudaEventRecord(evLN, 0);
                // S4 chain for next pass (s2) — overlaps next GEMM1
                cudaStreamWaitEvent(s2, evLN, 0);
                softmax_kernel<<<BB, 1024, 0, s2>>>(sc);
                wxpart_half_kernel<<<128, 512, 0, s2>>>(sc, xnatt, part);
                part_reduce_kernel<<<1, 512, 0, s2>>>(part, wxm, 128, 1.0f / BB);
                vecmat_split_kernel<<<8, 512, 0, s2>>>(wxm, s4_v, nullptr, nullptr, summ, DD, DD, 0);
                vecmat_split_kernel<<<12, 512, 0, s2>>>(summ, s4_sum, nullptr, reg_init, regsA, DD, RDR, 0);
            } else {
                lnx_kernel<1,1,0><<<NTOK, 256>>>(res, delta, gate, pw, p, nullptr,
                                                 m4_ln_s, m4_ln_b, kq, sc, xnatt, nullptr,
                                                 nullptr, nullptr, nullptr);
            }
            float* tmp = regs_cur; regs_cur = regs_nxt; regs_nxt = tmp;
        }
    }

    // ---- MetaS4 (main) ----
    softmax_kernel<<<BB, 1024>>>(sc);
    wxpart_half_kernel<<<128, 512>>>(sc, xnatt, part);
    part_reduce_kernel<<<BB, 512>>>(part, wxb, 32, 1.0f);
    {
        dim3 g(8, BB);
        vecmat_b4_kernel<<<g, 512>>>(wxb, m4_v, ms1);
        vecmat_b4_kernel<<<g, 512>>>(ms1, m4_out, mo);
    }
    lnx_kernel<2,2,0><<<NTOK, 256>>>(res, nullptr, nullptr, nullptr, 0, mo,
                                     out_ln_s, out_ln_b, nullptr, nullptr,
                                     nullptr, (float*)d_out, nullptr, nullptr, nullptr);
}

// round 14
// speedup vs baseline: 1.0643x; 1.0142x over previous
#include <cuda_runtime.h>
#include <cuda_fp16.h>
#include <math.h>
#include <stdint.h>

// ---------------- problem constants ----------------
#define BB 4
#define LL 2048
#define DD 512
#define DRR 256
#define RR 3
#define PP 5
#define PHH 3
#define FF 1536
#define NTOK (BB*LL)            // 8192
#define RDR (RR*DRR)            // 768

// ---------------- device scratch ----------------
__device__ __align__(256) float g_res[NTOK*DD];
__device__ __align__(256) float g_delta[NTOK*DD];
__device__ __align__(256) float g_sc[NTOK];
__device__ __align__(256) float g_part[128*DD];
__device__ __align__(256) float g_part1[64*FF];
__device__ __align__(256) float g_hsum[FF];
__device__ __align__(256) float g_q[DD];
__device__ __align__(256) float g_kq[DD];
__device__ __align__(256) float g_wxm[DD];
__device__ __align__(256) float g_summ[DD];
__device__ __align__(256) float g_regsA[RDR];
__device__ __align__(256) float g_regsB[RDR];
__device__ __align__(256) float g_gate[DD];
__device__ __align__(256) float g_banks[PP*RDR];
__device__ __align__(256) float g_pw[16];
__device__ __align__(256) float g_wxb[BB*DD];
__device__ __align__(256) float g_ms1[BB*DD];
__device__ __align__(256) float g_mo[BB*DD];

__device__ __align__(256) __half g_xnatt[NTOK*DD];
__device__ __align__(256) __half g_xnh[NTOK*DD];
__device__ __align__(256) __half g_hh[NTOK*FF];
__device__ __align__(256) __half g_w1th[PHH*FF*DD];
__device__ __align__(256) __half g_w2th[PHH*DD*FF];

// ---------------- PTX helpers ----------------
__device__ __forceinline__ uint32_t smem_u32(const void* p) {
    return (uint32_t)__cvta_generic_to_shared(p);
}
__device__ __forceinline__ void cpasync16(uint32_t dst, const void* src) {
    asm volatile("cp.async.cg.shared.global [%0], [%1], 16;" :: "r"(dst), "l"(src) : "memory");
}
__device__ __forceinline__ void cp_commit() {
    asm volatile("cp.async.commit_group;" ::: "memory");
}
__device__ __forceinline__ void cp_wait1() {
    asm volatile("cp.async.wait_group 1;" ::: "memory");
}
__device__ __forceinline__ void ldsm4(uint32_t* r, uint32_t addr) {
    asm volatile("ldmatrix.sync.aligned.m8n8.x4.shared.b16 {%0,%1,%2,%3}, [%4];"
                 : "=r"(r[0]), "=r"(r[1]), "=r"(r[2]), "=r"(r[3]) : "r"(addr));
}
__device__ __forceinline__ void mma16816(float* c, const uint32_t* a, uint32_t b0, uint32_t b1) {
    asm volatile(
        "mma.sync.aligned.m16n8k16.row.col.f32.f16.f16.f32 "
        "{%0,%1,%2,%3}, {%4,%5,%6,%7}, {%8,%9}, {%0,%1,%2,%3};"
        : "+f"(c[0]), "+f"(c[1]), "+f"(c[2]), "+f"(c[3])
        : "r"(a[0]), "r"(a[1]), "r"(a[2]), "r"(a[3]), "r"(b0), "r"(b1));
}

// ---------------- fp16 GEMM via mma.sync (row-split halves) ----------------
// mby0: row-block offset (grid.y covers a half: 32 blocks).
// MODE 1 (GEMM1): Ch = fp16(gelu(acc+bias)); part1[(by+mby0)*1536+col] = colsum.
// MODE 0 (GEMM2): Cf = acc + bias (delta).
#define STAGE_BYTES 32768
#define NSTAGE 3

template <int OUTMODE>
__global__ void __launch_bounds__(256, 2)
mmagemm_kernel(const __half* __restrict__ Ah, const __half* __restrict__ Bh,
               const float* __restrict__ bias,
               __half* __restrict__ Ch, float* __restrict__ part1,
               float* __restrict__ Cf, int mby0,
               int M, int N, int K) {
    extern __shared__ __align__(128) unsigned char smem[];

    const int tid  = threadIdx.x;
    const int wid  = tid >> 5;
    const int lane = tid & 31;
    const int n0 = blockIdx.x * 128;
    const int mby = blockIdx.y + mby0;
    const int m0 = mby * 128;
    const int NIT = K >> 6;
    const uint32_t smem_base = smem_u32(smem);

    int lrowA[4]; int lcA[4]; uint32_t ldst[4];
    #pragma unroll
    for (int u = 0; u < 4; u++) {
        int s = tid + u * 256;
        int row = s >> 3, c = s & 7;
        lrowA[u] = row; lcA[u] = c;
        ldst[u] = (uint32_t)(row * 128 + ((c ^ (row & 7)) << 4));
    }

    auto prefetch = [&](int it) {
        const int k0 = it << 6;
        const uint32_t st = smem_base + (uint32_t)(it % NSTAGE) * STAGE_BYTES;
        #pragma unroll
        for (int u = 0; u < 4; u++)
            cpasync16(st + ldst[u], Ah + (size_t)(m0 + lrowA[u]) * K + k0 + lcA[u] * 8);
        #pragma unroll
        for (int u = 0; u < 4; u++)
            cpasync16(st + 16384 + ldst[u], Bh + (size_t)(n0 + lrowA[u]) * K + k0 + lcA[u] * 8);
        cp_commit();
    };

    float acc[2][8][4];
    #pragma unroll
    for (int i = 0; i < 2; i++)
        #pragma unroll
        for (int j = 0; j < 8; j++)
            #pragma unroll
            for (int t = 0; t < 4; t++) acc[i][j][t] = 0.f;

    const int wm = (wid & 3) * 32;
    const int wn = (wid >> 2) * 64;
    const int lrow = lane & 15;
    const int lseg = lane >> 4;

    prefetch(0);
    if (NIT > 1) prefetch(1);

    #pragma unroll 1
    for (int it = 0; it < NIT; it++) {
        cp_wait1();
        __syncthreads();
        if (it + 2 < NIT) prefetch(it + 2);

        const uint32_t st = smem_base + (uint32_t)(it % NSTAGE) * STAGE_BYTES;
        #pragma unroll
        for (int kk = 0; kk < 4; kk++) {
            uint32_t af[2][4];
            #pragma unroll
            for (int i = 0; i < 2; i++) {
                int row = wm + i * 16 + lrow;
                int seg = kk * 2 + lseg;
                ldsm4(af[i], st + (uint32_t)(row * 128 + (((seg ^ (row & 7))) << 4)));
            }
            uint32_t bf[4][4];
            #pragma unroll
            for (int g = 0; g < 4; g++) {
                int row = wn + g * 16 + lrow;
                int seg = kk * 2 + lseg;
                ldsm4(bf[g], st + 16384u + (uint32_t)(row * 128 + (((seg ^ (row & 7))) << 4)));
            }
            #pragma unroll
            for (int i = 0; i < 2; i++)
                #pragma unroll
                for (int j = 0; j < 8; j++) {
                    int g = j >> 1, w = j & 1;
                    mma16816(acc[i][j], af[i], bf[g][w], bf[g][w + 2]);
                }
        }
    }

    const int l4 = lane >> 2;
    const int l2 = (lane & 3) * 2;

    if (OUTMODE == 1) {
        float vg[2][8][4];
        #pragma unroll
        for (int i = 0; i < 2; i++)
            #pragma unroll
            for (int j = 0; j < 8; j++) {
                const int col = n0 + wn + j * 8 + l2;
                const float b0v = bias[col], b1v = bias[col + 1];
                float t0 = acc[i][j][0] + b0v, t1 = acc[i][j][1] + b1v;
                float t2 = acc[i][j][2] + b0v, t3 = acc[i][j][3] + b1v;
                vg[i][j][0] = 0.5f * t0 * (1.0f + erff(t0 * 0.70710678118654752f));
                vg[i][j][1] = 0.5f * t1 * (1.0f + erff(t1 * 0.70710678118654752f));
                vg[i][j][2] = 0.5f * t2 * (1.0f + erff(t2 * 0.70710678118654752f));
                vg[i][j][3] = 0.5f * t3 * (1.0f + erff(t3 * 0.70710678118654752f));
            }
        float cs0[8], cs1[8];
        #pragma unroll
        for (int j = 0; j < 8; j++) {
            cs0[j] = vg[0][j][0] + vg[0][j][2] + vg[1][j][0] + vg[1][j][2];
            cs1[j] = vg[0][j][1] + vg[0][j][3] + vg[1][j][1] + vg[1][j][3];
            #pragma unroll
            for (int off = 4; off <= 16; off <<= 1) {
                cs0[j] += __shfl_xor_sync(0xffffffffu, cs0[j], off);
                cs1[j] += __shfl_xor_sync(0xffffffffu, cs1[j], off);
            }
        }
        __syncthreads();
        float* cs = (float*)smem;
        if (lane < 4) {
            #pragma unroll
            for (int j = 0; j < 8; j++) {
                cs[wid * 64 + j * 8 + lane * 2 + 0] = cs0[j];
                cs[wid * 64 + j * 8 + lane * 2 + 1] = cs1[j];
            }
        }
        __syncthreads();
        if (tid < 128) {
            int ng = tid >> 6, cw = tid & 63;
            float s = cs[(ng * 4 + 0) * 64 + cw] + cs[(ng * 4 + 1) * 64 + cw]
                    + cs[(ng * 4 + 2) * 64 + cw] + cs[(ng * 4 + 3) * 64 + cw];
            part1[(size_t)mby * FF + n0 + ng * 64 + cw] = s;
        }
        #pragma unroll
        for (int i = 0; i < 2; i++)
            #pragma unroll
            for (int j = 0; j < 8; j++) {
                const int col = n0 + wn + j * 8 + l2;
                const int row0 = m0 + wm + i * 16 + l4;
                unsigned short h0 = __half_as_ushort(__float2half_rn(vg[i][j][0]));
                unsigned short h1 = __half_as_ushort(__float2half_rn(vg[i][j][1]));
                unsigned short h2 = __half_as_ushort(__float2half_rn(vg[i][j][2]));
                unsigned short h3 = __half_as_ushort(__float2half_rn(vg[i][j][3]));
                *(ushort2*)((unsigned short*)Ch + (size_t)row0 * N + col)       = make_ushort2(h0, h1);
                *(ushort2*)((unsigned short*)Ch + (size_t)(row0 + 8) * N + col) = make_ushort2(h2, h3);
            }
    } else {
        #pragma unroll
        for (int i = 0; i < 2; i++)
            #pragma unroll
            for (int j = 0; j < 8; j++) {
                const int col = n0 + wn + j * 8 + l2;
                const int row0 = m0 + wm + i * 16 + l4;
                const float b0v = bias[col], b1v = bias[col + 1];
                *(float2*)(Cf + (size_t)row0 * N + col) =
                    make_float2(acc[i][j][0] + b0v, acc[i][j][1] + b1v);
                *(float2*)(Cf + (size_t)(row0 + 8) * N + col) =
                    make_float2(acc[i][j][2] + b0v, acc[i][j][3] + b1v);
            }
    }
}

// ---------------- fused residual-update + LayerNorm ----------------
template <int INMODE, int XNMODE, int EMIT_XNH>
__global__ void lnx_kernel(float* __restrict__ res,
                           const float* __restrict__ delta, const float* __restrict__ gate,
                           const float* __restrict__ pw, int p,
                           const float* __restrict__ mo,
                           const float* __restrict__ sA, const float* __restrict__ bA,
                           const float* __restrict__ kq, float* __restrict__ score,
                           __half* __restrict__ xn, float* __restrict__ outf,
                           const float* __restrict__ sB, const float* __restrict__ bB,
                           __half* __restrict__ xnh) {
    __shared__ float red[256];
    int t = blockIdx.x;
    int tid = threadIdx.x;
    float2 v = ((const float2*)res)[(size_t)t * 256 + tid];
    if (INMODE == 1) {
        float w = pw[p];
        float2 d = ((const float2*)delta)[(size_t)t * 256 + tid];
        float2 g = ((const float2*)gate)[tid];
        v.x += w * g.x * d.x;
        v.y += w * g.y * d.y;
        ((float2*)res)[(size_t)t * 256 + tid] = v;
    } else if (INMODE == 2) {
        int b = t >> 11;
        float2 m = ((const float2*)mo)[(b << 8) + tid];
        v.x += m.x; v.y += m.y;
    }
    red[tid] = v.x + v.y; __syncthreads();
    #pragma unroll
    for (int o = 128; o > 0; o >>= 1) { if (tid < o) red[tid] += red[tid + o]; __syncthreads(); }
    float mean = red[0] * (1.0f / 512.0f);
    __syncthreads();
    float d0 = v.x - mean, d1 = v.y - mean;
    red[tid] = d0 * d0 + d1 * d1; __syncthreads();
    #pragma unroll
    for (int o = 128; o > 0; o >>= 1) { if (tid < o) red[tid] += red[tid + o]; __syncthreads(); }
    float rstd = rsqrtf(red[0] * (1.0f / 512.0f) + 1e-5f);
    __syncthreads();
    if (XNMODE) {
        float2 s = ((const float2*)sA)[tid];
        float2 b = ((const float2*)bA)[tid];
        float y0 = d0 * rstd * s.x + b.x;
        float y1 = d1 * rstd * s.y + b.y;
        if (XNMODE == 1) {
            ((__half2*)xn)[(size_t)t * 256 + tid] =
                __halves2half2(__float2half_rn(y0), __float2half_rn(y1));
            float2 k = ((const float2*)kq)[tid];
            red[tid] = y0 * k.x + y1 * k.y; __syncthreads();
            #pragma unroll
            for (int o = 128; o > 0; o >>= 1) { if (tid < o) red[tid] += red[tid + o]; __syncthreads(); }
            if (tid == 0) score[t] = red[0] * 0.044194173824159216f;
        } else {
            ((float2*)outf)[(size_t)t * 256 + tid] = make_float2(y0, y1);
        }
    }
    if (EMIT_XNH) {
        float2 s = ((const float2*)sB)[tid];
        float2 b = ((const float2*)bB)[tid];
        float z0 = d0 * rstd * s.x + b.x;
        float z1 = d1 * rstd * s.y + b.y;
        ((__half2*)xnh)[(size_t)t * 256 + tid] =
            __halves2half2(__float2half_rn(z0), __float2half_rn(z1));
    }
}

// ---------------- hsum: column sums of part1 (64 x 1536) ----------------
__global__ void colsumH_kernel(const float* __restrict__ part1, float* __restrict__ hsum) {
    int col = blockIdx.x * 512 + threadIdx.x;
    float acc = 0.f;
    #pragma unroll 8
    for (int c = 0; c < 64; c++)
        acc += part1[(size_t)c * FF + col];
    hsum[col] = acc;
}

// ---------------- summary: summ[j] = hsum@w2[:,j]/NTOK + b2[j] ----------------
__global__ void summk_kernel(const float* __restrict__ hsum, const __half* __restrict__ w2t,
                             const float* __restrict__ b2, float* __restrict__ summ) {
    __shared__ float red[128];
    int j = blockIdx.x;
    int tid = threadIdx.x;
    const __half* row = w2t + (size_t)j * FF;
    float acc = 0.f;
    #pragma unroll
    for (int k = tid; k < FF; k += 128)
        acc += hsum[k] * __half2float(row[k]);
    red[tid] = acc; __syncthreads();
    #pragma unroll
    for (int o = 64; o > 0; o >>= 1) { if (tid < o) red[tid] += red[tid + o]; __syncthreads(); }
    if (tid == 0) summ[j] = red[0] * (1.0f / (float)NTOK) + b2[j];
}

// ---------------- gate + register update (11 blocks x 512) ----------------
__global__ void gatereg_kernel(const float* __restrict__ summ, const float* __restrict__ regs_cur,
                               const float* __restrict__ gM, const float* __restrict__ gb,
                               float* __restrict__ gate,
                               const float* __restrict__ Wp, const float* __restrict__ Wg,
                               const float* __restrict__ bg,
                               float* __restrict__ regs_next, float* __restrict__ banks) {
    __shared__ float red[512];
    int tid = threadIdx.x;
    if (blockIdx.x < 8) {
        int j = blockIdx.x * 64 + (tid & 63);
        int s = tid >> 6;
        float a = 0.f;
        #pragma unroll 8
        for (int d = s * 160; d < s * 160 + 160; d++) {
            float v = (d < RDR) ? regs_cur[d] : summ[d - RDR];
            a += v * gM[(size_t)d * DD + j];
        }
        red[tid] = a; __syncthreads();
        if (tid < 64) {
            float g = 0.f;
            #pragma unroll
            for (int k = 0; k < 8; k++) g += red[k * 64 + tid];
            g += gb[j];
            gate[j] = 1.f / (1.f + expf(-g));
        }
    } else {
        __shared__ float shw;
        int r = blockIdx.x - 8;
        red[tid] = summ[tid] * Wg[(size_t)r * DD + tid];
        __syncthreads();
        #pragma unroll
        for (int o = 256; o > 0; o >>= 1) { if (tid < o) red[tid] += red[tid + o]; __syncthreads(); }
        if (tid == 0) shw = 1.f / (1.f + expf(-(red[0] + bg[r])));
        __syncthreads();
        int k = tid & 255, s = tid >> 8;
        const float* W = Wp + (size_t)r * DD * DRR;
        float a = 0.f;
        #pragma unroll 16
        for (int d = s * 256; d < (s + 1) * 256; d++)
            a += summ[d] * W[(size_t)d * DRR + k];
        red[tid] = a; __syncthreads();
        if (tid < 256) {
            float nv = regs_cur[r * DRR + k] + shw * (red[k] + red[k + 256]);
            regs_next[r * DRR + k] = nv;
            if (banks) banks[r * DRR + k] = nv;
        }
    }
}

// ---------------- k-split vec @ mat (fp32) ----------------
__global__ void vecmat_split_kernel(const float* __restrict__ v, const float* __restrict__ M,
                                    const float* __restrict__ bias, const float* __restrict__ init,
                                    float* __restrict__ out, int nrow, int ncol, int act) {
    __shared__ float red[512];
    int tid = threadIdx.x;
    int j = blockIdx.x * 64 + (tid & 63);
    int s = tid >> 6;
    int sl = nrow >> 3;
    float acc = 0.f;
    #pragma unroll 16
    for (int d = s * sl; d < (s + 1) * sl; d++)
        acc += v[d] * M[(size_t)d * ncol + j];
    red[tid] = acc; __syncthreads();
    if (tid < 64) {
        float a = 0.f;
        #pragma unroll
        for (int k = 0; k < 8; k++) a += red[k * 64 + tid];
        if (bias) a += bias[j];
        if (init) a += init[j];
        if (act == 1) a = 1.f / (1.f + expf(-a));
        out[j] = a;
    }
}

// batched (4x) 512x512 vec@mat
__global__ void vecmat_b4_kernel(const float* __restrict__ v, const float* __restrict__ M,
                                 float* __restrict__ out) {
    __shared__ float red[512];
    int tid = threadIdx.x;
    int b = blockIdx.y;
    int j = blockIdx.x * 64 + (tid & 63);
    int s = tid >> 6;
    const float* vb = v + (size_t)b * DD;
    float acc = 0.f;
    #pragma unroll 16
    for (int d = s * 64; d < (s + 1) * 64; d++)
        acc += vb[d] * M[(size_t)d * DD + j];
    red[tid] = acc; __syncthreads();
    if (tid < 64) {
        float a = 0.f;
        #pragma unroll
        for (int k = 0; k < 8; k++) a += red[k * 64 + tid];
        out[(size_t)b * DD + j] = a;
    }
}

// ---------------- other small kernels ----------------

__global__ void transpose_all_kernel(const float* __restrict__ w1, const float* __restrict__ w2,
                                     __half* __restrict__ w1t, __half* __restrict__ w2t) {
    __shared__ float tl[32][33];
    int bid = blockIdx.x;
    int m = bid / 768;
    int t = bid % 768;
    const float* src; __half* dst; int R, C;
    if (m < 3) { src = w1 + (size_t)m * DD * FF; dst = w1t + (size_t)m * FF * DD; R = DD; C = FF; }
    else { int ph = m - 3; src = w2 + (size_t)ph * FF * DD; dst = w2t + (size_t)ph * DD * FF; R = FF; C = DD; }
    int tpr = C >> 5;
    int ty = t / tpr, tx = t % tpr;
    int r = ty * 32 + threadIdx.y, c = tx * 32 + threadIdx.x;
    tl[threadIdx.y][threadIdx.x] = src[(size_t)r * C + c];
    __syncthreads();
    int orow = tx * 32 + threadIdx.y, ocol = ty * 32 + threadIdx.x;
    dst[(size_t)orow * R + ocol] = __float2half_rn(tl[threadIdx.x][threadIdx.y]);
}

__global__ void copy4_kernel(const float4* __restrict__ src, float4* __restrict__ dst) {
    size_t i = (size_t)blockIdx.x * blockDim.x + threadIdx.x;
    dst[i] = src[i];
}

__global__ void passw_kernel(const float* __restrict__ reg_init,
                             const float* __restrict__ W,
                             const float* __restrict__ b,
                             float* __restrict__ pw) {
    __shared__ float red[256];
    int p = blockIdx.x;
    int tid = threadIdx.x;
    float acc = 0.f;
    for (int i = tid; i < PP * RDR; i += 256)
        acc += reg_init[i % RDR] * W[i * PP + p];
    red[tid] = acc; __syncthreads();
    #pragma unroll
    for (int o = 128; o > 0; o >>= 1) { if (tid < o) red[tid] += red[tid + o]; __syncthreads(); }
    if (tid == 0) pw[p] = 1.f / (1.f + expf(-(red[0] + b[p])));
}

__global__ void matvec_kernel(const float* __restrict__ M,
                              const float* __restrict__ v,
                              float* __restrict__ out) {
    __shared__ float red[128];
    int r = blockIdx.x;
    int tid = threadIdx.x;
    float acc = 0.f;
    #pragma unroll
    for (int j = tid; j < DD; j += 128)
        acc += M[(size_t)r * DD + j] * v[j];
    red[tid] = acc; __syncthreads();
    for (int o = 64; o > 0; o >>= 1) {
        if (tid < o) red[tid] += red[tid + o];
        __syncthreads();
    }
    if (tid == 0) out[r] = red[0];
}

__global__ void softmax_kernel(float* __restrict__ sc) {
    __shared__ float red[1024];
    int b = blockIdx.x;
    float* p = sc + (size_t)b * LL;
    int tid = threadIdx.x;
    float v0 = p[tid], v1 = p[tid + 1024];
    red[tid] = fmaxf(v0, v1); __syncthreads();
    #pragma unroll
    for (int o = 512; o > 0; o >>= 1) { if (tid < o) red[tid] = fmaxf(red[tid], red[tid + o]); __syncthreads(); }
    float mx = red[0];
    __syncthreads();
    float e0 = expf(v0 - mx), e1 = expf(v1 - mx);
    red[tid] = e0 + e1; __syncthreads();
    #pragma unroll
    for (int o = 512; o > 0; o >>= 1) { if (tid < o) red[tid] += red[tid + o]; __syncthreads(); }
    float inv = 1.f / red[0];
    p[tid] = e0 * inv;
    p[tid + 1024] = e1 * inv;
}

__global__ void wxpart_half_kernel(const float* __restrict__ a, const __half* __restrict__ xn,
                                   float* __restrict__ part) {
    int d = threadIdx.x;
    int blk = blockIdx.x;
    int row0 = blk * 64;
    float acc = 0.f;
    #pragma unroll 8
    for (int r = row0; r < row0 + 64; r++)
        acc += a[r] * __half2float(xn[(size_t)r * DD + d]);
    part[(size_t)blk * DD + d] = acc;
}

__global__ void part_reduce_kernel(const float* __restrict__ part, float* __restrict__ out,
                                   int nchunk, float scale) {
    int d = threadIdx.x;
    int g = blockIdx.x;
    const float* p = part + (size_t)g * nchunk * DD;
    float acc = 0.f;
    #pragma unroll 8
    for (int c = 0; c < nchunk; c++)
        acc += p[(size_t)c * DD + d];
    out[(size_t)g * DD + d] = acc * scale;
}

// ---------------- host orchestration ----------------

extern "C" void kernel_launch(void* const* d_in, const int* in_sizes, int n_in,
                              void* d_out, int out_size) {
    const float* x        = (const float*)d_in[0];
    const float* reg_init = (const float*)d_in[1];
    const float* ffn_ln_s = (const float*)d_in[2];
    const float* ffn_ln_b = (const float*)d_in[3];
    const float* ffn_w1   = (const float*)d_in[4];
    const float* ffn_b1   = (const float*)d_in[5];
    const float* ffn_w2   = (const float*)d_in[6];
    const float* ffn_b2   = (const float*)d_in[7];
    const float* gate_w   = (const float*)d_in[8];
    const float* gate_b   = (const float*)d_in[9];
    const float* wproj_w  = (const float*)d_in[10];
    const float* wgate_w  = (const float*)d_in[11];
    const float* wgate_b  = (const float*)d_in[12];
    const float* s4_q     = (const float*)d_in[13];
    const float* s4_k     = (const float*)d_in[14];
    const float* s4_v     = (const float*)d_in[15];
    const float* s4_sum   = (const float*)d_in[16];
    const float* s4_ln_s  = (const float*)d_in[17];
    const float* s4_ln_b  = (const float*)d_in[18];
    const float* ms3_w    = (const float*)d_in[19];
    const float* ms3_b    = (const float*)d_in[20];
    const float* m4_q     = (const float*)d_in[21];
    const float* m4_k     = (const float*)d_in[22];
    const float* m4_v     = (const float*)d_in[23];
    const float* m4_out   = (const float*)d_in[24];
    const float* m4_ln_s  = (const float*)d_in[25];
    const float* m4_ln_b  = (const float*)d_in[26];
    const float* out_ln_s = (const float*)d_in[27];
    const float* out_ln_b = (const float*)d_in[28];

    float *res, *delta, *sc, *part, *part1, *hsum, *q, *kq, *wxm, *summ, *gate;
    float *regsA, *regsB, *banks, *pw, *wxb, *ms1, *mo;
    __half *xnatt, *xnh, *hh, *w1th, *w2th;
    cudaGetSymbolAddress((void**)&res,   g_res);
    cudaGetSymbolAddress((void**)&delta, g_delta);
    cudaGetSymbolAddress((void**)&sc,    g_sc);
    cudaGetSymbolAddress((void**)&part,  g_part);
    cudaGetSymbolAddress((void**)&part1, g_part1);
    cudaGetSymbolAddress((void**)&hsum,  g_hsum);
    cudaGetSymbolAddress((void**)&q,     g_q);
    cudaGetSymbolAddress((void**)&kq,    g_kq);
    cudaGetSymbolAddress((void**)&wxm,   g_wxm);
    cudaGetSymbolAddress((void**)&summ,  g_summ);
    cudaGetSymbolAddress((void**)&gate,  g_gate);
    cudaGetSymbolAddress((void**)&regsA, g_regsA);
    cudaGetSymbolAddress((void**)&regsB, g_regsB);
    cudaGetSymbolAddress((void**)&banks, g_banks);
    cudaGetSymbolAddress((void**)&pw,    g_pw);
    cudaGetSymbolAddress((void**)&wxb,   g_wxb);
    cudaGetSymbolAddress((void**)&ms1,   g_ms1);
    cudaGetSymbolAddress((void**)&mo,    g_mo);
    cudaGetSymbolAddress((void**)&xnatt, g_xnatt);
    cudaGetSymbolAddress((void**)&xnh,   g_xnh);
    cudaGetSymbolAddress((void**)&hh,    g_hh);
    cudaGetSymbolAddress((void**)&w1th,  g_w1th);
    cudaGetSymbolAddress((void**)&w2th,  g_w2th);

    const int ELEM = NTOK * DD;

    // one side stream (same topology class as R12, which passes all harness checks)
    static cudaStream_t s2 = nullptr;
    static cudaEvent_t e0, eT, e1a, e1b, evS2, evLN;
    if (!s2) {
        cudaStreamCreateWithFlags(&s2, cudaStreamNonBlocking);
        cudaEventCreateWithFlags(&e0,  cudaEventDisableTiming);
        cudaEventCreateWithFlags(&eT,  cudaEventDisableTiming);
        cudaEventCreateWithFlags(&e1a, cudaEventDisableTiming);
        cudaEventCreateWithFlags(&e1b, cudaEventDisableTiming);
        cudaEventCreateWithFlags(&evS2, cudaEventDisableTiming);
        cudaEventCreateWithFlags(&evLN, cudaEventDisableTiming);
    }

    cudaFuncSetAttribute(mmagemm_kernel<0>, cudaFuncAttributeMaxDynamicSharedMemorySize, NSTAGE * STAGE_BYTES);
    cudaFuncSetAttribute(mmagemm_kernel<1>, cudaFuncAttributeMaxDynamicSharedMemorySize, NSTAGE * STAGE_BYTES);

    // fork: transposes + passw on s2 overlap the main-stream prologue
    cudaEventRecord(e0, 0);
    cudaStreamWaitEvent(s2, e0, 0);
    {
        dim3 blk(32, 32);
        transpose_all_kernel<<<6 * 768, blk, 0, s2>>>(ffn_w1, ffn_w2, w1th, w2th);
        passw_kernel<<<PP, 256, 0, s2>>>(reg_init, ms3_w, ms3_b, pw);
        cudaEventRecord(eT, s2);
    }
    copy4_kernel<<<ELEM / 4 / 256, 256>>>((const float4*)x, (float4*)res);
    vecmat_split_kernel<<<8, 512>>>(banks, s4_q, nullptr, nullptr, q, 0, DD, 0);
    matvec_kernel<<<512, 128>>>(s4_k, q, kq);
    lnx_kernel<0,1,1><<<NTOK, 256>>>(res, nullptr, nullptr, nullptr, 0, nullptr,
                                     s4_ln_s, s4_ln_b, kq, sc, xnatt, nullptr,
                                     ffn_ln_s, ffn_ln_b, xnh);
    softmax_kernel<<<BB, 1024>>>(sc);
    wxpart_half_kernel<<<128, 512>>>(sc, xnatt, part);
    part_reduce_kernel<<<1, 512>>>(part, wxm, 128, 1.0f / BB);
    vecmat_split_kernel<<<8, 512>>>(wxm, s4_v, nullptr, nullptr, summ, DD, DD, 0);
    vecmat_split_kernel<<<12, 512>>>(summ, s4_sum, nullptr, reg_init, regsA, DD, RDR, 0);
    cudaStreamWaitEvent(0, eT, 0);   // transposes+pw ready before first GEMM1 / LN use
    cudaEventRecord(evLN, 0);        // baseline "inputs ready" for first G1b on s2

    for (int p = 0; p < PP; p++) {
        float* regs_cur = regsA;
        float* regs_nxt = regsB;
        for (int ph = 0; ph < PHH; ph++) {
            const int pp = p * PHH + ph;
            const __half* w1p = w1th + (size_t)ph * FF * DD;
            const __half* w2p = w2th + (size_t)ph * DD * FF;
            const float*  b1p = ffn_b1 + (size_t)ph * FF;
            const float*  b2p = ffn_b2 + (size_t)ph * DD;
            dim3 g1grid(FF / 128, 32);
            dim3 g2grid(DD / 128, 32);
            // G1a on main (rows 0-31); G1b on s2 (rows 32-63) — halves pack
            mmagemm_kernel<1><<<g1grid, 256, NSTAGE * STAGE_BYTES>>>(
                xnh, w1p, b1p, hh, part1, nullptr, 0, NTOK, FF, DD);
            cudaEventRecord(e1a, 0);
            cudaStreamWaitEvent(s2, evLN, 0);
            mmagemm_kernel<1><<<g1grid, 256, NSTAGE * STAGE_BYTES, s2>>>(
                xnh, w1p, b1p, hh, part1, nullptr, 32, NTOK, FF, DD);
            cudaEventRecord(e1b, s2);
            // G2a on main (needs only G1a rows; fills G1b tail slots)
            mmagemm_kernel<0><<<g2grid, 256, NSTAGE * STAGE_BYTES>>>(
                hh, w2p, b2p, nullptr, nullptr, delta, 0, NTOK, DD, FF);
            // s2: summary chain (needs full part1; e1a from main, e1b by program order)
            cudaStreamWaitEvent(s2, e1a, 0);
            colsumH_kernel<<<3, 512, 0, s2>>>(part1, hsum);
            summk_kernel<<<512, 128, 0, s2>>>(hsum, w2p, b2p, summ);
            gatereg_kernel<<<11, 512, 0, s2>>>(summ, regs_cur,
                                               gate_w + (size_t)pp * (RDR + DD) * DD,
                                               gate_b + (size_t)pp * DD, gate,
                                               wproj_w + (size_t)pp * RR * DD * DRR,
                                               wgate_w + (size_t)pp * RR * DD,
                                               wgate_b + (size_t)pp * RR,
                                               regs_nxt,
                                               (ph == PHH - 1) ? (banks + (size_t)p * RDR) : nullptr);
            if (ph == PHH - 1) {
                if (p < PP - 1) {
                    vecmat_split_kernel<<<8, 512, 0, s2>>>(banks, s4_q, nullptr, nullptr, q,
                                                           (p + 1) * RDR, DD, 0);
                    matvec_kernel<<<512, 128, 0, s2>>>(s4_k, q, kq);
                } else {
                    vecmat_split_kernel<<<8, 512, 0, s2>>>(banks, m4_q, nullptr, nullptr, q,
                                                           PP * RDR, DD, 0);
                    matvec_kernel<<<512, 128, 0, s2>>>(m4_k, q, kq);
                }
            }
            cudaEventRecord(evS2, s2);
            // G2b on main after G1b done
            cudaStreamWaitEvent(0, e1b, 0);
            mmagemm_kernel<0><<<g2grid, 256, NSTAGE * STAGE_BYTES>>>(
                hh, w2p, b2p, nullptr, nullptr, delta, 32, NTOK, DD, FF);
            // LN on main (program order covers G2a/G2b) + chain result
            cudaStreamWaitEvent(0, evS2, 0);
            if (ph < PHH - 1) {
                lnx_kernel<1,0,1><<<NTOK, 256>>>(res, delta, gate, pw, p, nullptr,
                                                 nullptr, nullptr, nullptr, nullptr,
                                                 nullptr, nullptr,
                                                 ffn_ln_s + (size_t)(ph + 1) * DD,
                                                 ffn_ln_b + (size_t)(ph + 1) * DD, xnh);
            } else if (p < PP - 1) {
                lnx_kernel<1,1,1><<<NTOK, 256>>>(res, delta, gate, pw, p, nullptr,
                                                 s4_ln_s, s4_ln_b, kq, sc, xnatt, nullptr,
                                                 ffn_ln_s, ffn_ln_b, xnh);
            } else {
                lnx_kernel<1,1,0><<<NTOK, 256>>>(res, delta, gate, pw, p, nullptr,
                                                 m4_ln_s, m4_ln_b, kq, sc, xnatt, nullptr,
                                                 nullptr, nullptr, nullptr);
            }
            cudaEventRecord(evLN, 0);
            if (ph == PHH - 1 && p < PP - 1) {
                // next pass S4 chain on s2 (overlaps next GEMM1)
                cudaStreamWaitEvent(s2, evLN, 0);
                softmax_kernel<<<BB, 1024, 0, s2>>>(sc);
                wxpart_half_kernel<<<128, 512, 0, s2>>>(sc, xnatt, part);
                part_reduce_kernel<<<1, 512, 0, s2>>>(part, wxm, 128, 1.0f / BB);
                vecmat_split_kernel<<<8, 512, 0, s2>>>(wxm, s4_v, nullptr, nullptr, summ, DD, DD, 0);
                vecmat_split_kernel<<<12, 512, 0, s2>>>(summ, s4_sum, nullptr, reg_init, regsA, DD, RDR, 0);
            }
            float* tmp = regs_cur; regs_cur = regs_nxt; regs_nxt = tmp;
        }
    }

    // ---- MetaS4 (main) ----
    softmax_kernel<<<BB, 1024>>>(sc);
    wxpart_half_kernel<<<128, 512>>>(sc, xnatt, part);
    part_reduce_kernel<<<BB, 512>>>(part, wxb, 32, 1.0f);
    {
        dim3 g(8, BB);
        vecmat_b4_kernel<<<g, 512>>>(wxb, m4_v, ms1);
        vecmat_b4_kernel<<<g, 512>>>(ms1, m4_out, mo);
    }
    lnx_kernel<2,2,0><<<NTOK, 256>>>(res, nullptr, nullptr, nullptr, 0, mo,
                                     out_ln_s, out_ln_b, nullptr, nullptr,
                                     nullptr, (float*)d_out, nullptr, nullptr, nullptr);
}